// round 1
// baseline (speedup 1.0000x reference)
#include <cuda_runtime.h>
#include <math.h>

// Problem constants (fixed shapes from reference)
#define D_MODEL 1024
#define N_HEADS 16
#define HEAD_D  64
#define NB      2
#define LSEQ    2048
#define MTOT    (NB * LSEQ)   // 4096 rows total

// Scratch buffers (allocation-free rule: __device__ globals)
__device__ float g_q[(size_t)MTOT * D_MODEL];
__device__ float g_k[(size_t)MTOT * D_MODEL];
__device__ float g_v[(size_t)MTOT * D_MODEL];
__device__ float g_attn[(size_t)MTOT * D_MODEL];

// ---------------------------------------------------------------------------
// GEMM with bias: C[m,n] = sum_k X[m,k] * W[n,k] + bias[n]
// (torch Linear: x @ W.T + b; both X and W are K-contiguous row-major)
// 128x128 block tile, BK=16, 256 threads, 8x8 register microtile.
// ---------------------------------------------------------------------------
#define BM  128
#define BN  128
#define BKK 16

__global__ __launch_bounds__(256, 2)
void gemm_bias_kernel(const float* __restrict__ X, const float* __restrict__ W,
                      const float* __restrict__ bias, float* __restrict__ C,
                      int M, int N, int K)
{
    __shared__ float As[BKK][BM];   // As[k][m]  (transposed X tile)
    __shared__ float Bs[BKK][BN];   // Bs[k][n]  (transposed W tile)

    const int tid = threadIdx.x;
    const int tx  = tid & 15;   // 0..15 -> output cols (8 each)
    const int ty  = tid >> 4;   // 0..15 -> output rows (8 each)
    const int bm  = blockIdx.y * BM;
    const int bn  = blockIdx.x * BN;

    float acc[8][8];
#pragma unroll
    for (int i = 0; i < 8; i++)
#pragma unroll
        for (int j = 0; j < 8; j++) acc[i][j] = 0.f;

    for (int kt = 0; kt < K; kt += BKK) {
        // Load 128x16 tiles of X and W, transposed into smem. Coalesced float4.
#pragma unroll
        for (int i = 0; i < 2; i++) {
            int f  = tid + i * 256;      // 0..511 float4 index
            int r  = f >> 2;             // 0..127 tile row
            int c4 = (f & 3) << 2;       // 0,4,8,12

            float4 va = *(const float4*)(X + (size_t)(bm + r) * K + kt + c4);
            As[c4 + 0][r] = va.x; As[c4 + 1][r] = va.y;
            As[c4 + 2][r] = va.z; As[c4 + 3][r] = va.w;

            float4 vb = *(const float4*)(W + (size_t)(bn + r) * K + kt + c4);
            Bs[c4 + 0][r] = vb.x; Bs[c4 + 1][r] = vb.y;
            Bs[c4 + 2][r] = vb.z; Bs[c4 + 3][r] = vb.w;
        }
        __syncthreads();

#pragma unroll
        for (int k = 0; k < BKK; k++) {
            float4 a0 = *(const float4*)(&As[k][ty * 8]);
            float4 a1 = *(const float4*)(&As[k][ty * 8 + 4]);
            float4 b0 = *(const float4*)(&Bs[k][tx * 8]);
            float4 b1 = *(const float4*)(&Bs[k][tx * 8 + 4]);
            float a[8] = {a0.x, a0.y, a0.z, a0.w, a1.x, a1.y, a1.z, a1.w};
            float b[8] = {b0.x, b0.y, b0.z, b0.w, b1.x, b1.y, b1.z, b1.w};
#pragma unroll
            for (int i = 0; i < 8; i++)
#pragma unroll
                for (int j = 0; j < 8; j++)
                    acc[i][j] += a[i] * b[j];
        }
        __syncthreads();
    }

    // Epilogue: add bias, vectorized stores
#pragma unroll
    for (int i = 0; i < 8; i++) {
        int row = bm + ty * 8 + i;
#pragma unroll
        for (int j = 0; j < 8; j += 4) {
            int col = bn + tx * 8 + j;
            float4 o;
            o.x = acc[i][j + 0] + bias[col + 0];
            o.y = acc[i][j + 1] + bias[col + 1];
            o.z = acc[i][j + 2] + bias[col + 2];
            o.w = acc[i][j + 3] + bias[col + 3];
            *(float4*)(C + (size_t)row * N + col) = o;
        }
    }
}

// ---------------------------------------------------------------------------
// Flash attention (causal), head dim 64.
// Block handles one 64-row Q tile of one (batch, head). 128 threads.
// Thread grid 16(tx: cols) x 8(ty: rows); microtile 8 rows x 4 cols.
// Online softmax; key tiles limited to kt <= qt (causal skip).
// Smem: Q^T[64][65], K^T[64][65], V[64][65], P[64][65]  -> 66560 B (dynamic).
// ---------------------------------------------------------------------------
#define BR 64
#define BC 64
#define SROW 65
#define ATTN_SMEM (4 * 64 * SROW * (int)sizeof(float))

__global__ __launch_bounds__(128, 2)
void flash_attn_kernel(const float* __restrict__ Qb, const float* __restrict__ Kb,
                       const float* __restrict__ Vb, float* __restrict__ Ob)
{
    extern __shared__ float smbuf[];
    float* Qts = smbuf;                        // Qts[d*SROW + r] = Q[r][d]
    float* Kts = smbuf + 64 * SROW;            // Kts[d*SROW + c] = K[c][d]
    float* Vsm = smbuf + 2 * 64 * SROW;        // Vsm[c*SROW + d] = V[c][d]
    float* Psm = smbuf + 3 * 64 * SROW;        // Psm[r*SROW + c]

    const int tid = threadIdx.x;
    const int tx  = tid & 15;   // 0..15
    const int ty  = tid >> 4;   // 0..7
    const int qt  = blockIdx.x;
    const int h   = blockIdx.y;
    const int n   = blockIdx.z;

    const float scale = 0.125f;  // 1/sqrt(64)

    // Load Q tile, transposed into smem (coalesced float4 gmem reads)
    const float* Qg = Qb + ((size_t)n * LSEQ + (size_t)qt * BR) * D_MODEL + h * HEAD_D;
#pragma unroll
    for (int i = 0; i < 8; i++) {
        int f   = tid + i * 128;     // 0..1023 float4 index
        int row = f >> 4;            // 0..63
        int c4  = (f & 15) << 2;     // 0..60
        float4 v = *(const float4*)(Qg + (size_t)row * D_MODEL + c4);
        Qts[(c4 + 0) * SROW + row] = v.x;
        Qts[(c4 + 1) * SROW + row] = v.y;
        Qts[(c4 + 2) * SROW + row] = v.z;
        Qts[(c4 + 3) * SROW + row] = v.w;
    }

    float m_i[8], l_i[8], acc[8][4];
#pragma unroll
    for (int i = 0; i < 8; i++) {
        m_i[i] = -INFINITY;
        l_i[i] = 0.f;
#pragma unroll
        for (int j = 0; j < 4; j++) acc[i][j] = 0.f;
    }

    for (int kt = 0; kt <= qt; kt++) {
        const float* Kg = Kb + ((size_t)n * LSEQ + (size_t)kt * BC) * D_MODEL + h * HEAD_D;
        const float* Vg = Vb + ((size_t)n * LSEQ + (size_t)kt * BC) * D_MODEL + h * HEAD_D;

        __syncthreads();   // previous iteration done reading K/V (also orders Q writes on iter 0)
#pragma unroll
        for (int i = 0; i < 8; i++) {
            int f   = tid + i * 128;
            int row = f >> 4;
            int c4  = (f & 15) << 2;
            float4 kv = *(const float4*)(Kg + (size_t)row * D_MODEL + c4);
            Kts[(c4 + 0) * SROW + row] = kv.x;
            Kts[(c4 + 1) * SROW + row] = kv.y;
            Kts[(c4 + 2) * SROW + row] = kv.z;
            Kts[(c4 + 3) * SROW + row] = kv.w;
            float4 vv = *(const float4*)(Vg + (size_t)row * D_MODEL + c4);
            Vsm[row * SROW + c4 + 0] = vv.x;
            Vsm[row * SROW + c4 + 1] = vv.y;
            Vsm[row * SROW + c4 + 2] = vv.z;
            Vsm[row * SROW + c4 + 3] = vv.w;
        }
        __syncthreads();

        // Scores: sc[i][j] = Q[row] . K[col]
        float sc[8][4];
#pragma unroll
        for (int i = 0; i < 8; i++)
#pragma unroll
            for (int j = 0; j < 4; j++) sc[i][j] = 0.f;

#pragma unroll 8
        for (int d = 0; d < HEAD_D; d++) {
            float a[8], b[4];
#pragma unroll
            for (int i = 0; i < 8; i++) a[i] = Qts[d * SROW + ty * 8 + i];
#pragma unroll
            for (int j = 0; j < 4; j++) b[j] = Kts[d * SROW + tx * 4 + j];
#pragma unroll
            for (int i = 0; i < 8; i++)
#pragma unroll
                for (int j = 0; j < 4; j++)
                    sc[i][j] += a[i] * b[j];
        }

        // Scale + causal mask (diagonal tile only)
        if (kt == qt) {
#pragma unroll
            for (int i = 0; i < 8; i++) {
                int rl = ty * 8 + i;
#pragma unroll
                for (int j = 0; j < 4; j++) {
                    int cl = tx * 4 + j;
                    sc[i][j] = (cl > rl) ? -INFINITY : sc[i][j] * scale;
                }
            }
        } else {
#pragma unroll
            for (int i = 0; i < 8; i++)
#pragma unroll
                for (int j = 0; j < 4; j++) sc[i][j] *= scale;
        }

        // Online softmax update (row stats reduced over 16 lanes sharing ty)
#pragma unroll
        for (int i = 0; i < 8; i++) {
            float mx = fmaxf(fmaxf(sc[i][0], sc[i][1]), fmaxf(sc[i][2], sc[i][3]));
            mx = fmaxf(mx, __shfl_xor_sync(0xffffffffu, mx, 1));
            mx = fmaxf(mx, __shfl_xor_sync(0xffffffffu, mx, 2));
            mx = fmaxf(mx, __shfl_xor_sync(0xffffffffu, mx, 4));
            mx = fmaxf(mx, __shfl_xor_sync(0xffffffffu, mx, 8));
            float m_new = fmaxf(m_i[i], mx);
            float corr  = __expf(m_i[i] - m_new);   // 0 on first tile (m_i=-inf)
            float ls = 0.f;
#pragma unroll
            for (int j = 0; j < 4; j++) {
                float p = __expf(sc[i][j] - m_new);  // masked -> exp(-inf)=0
                Psm[(ty * 8 + i) * SROW + tx * 4 + j] = p;
                ls += p;
            }
            ls += __shfl_xor_sync(0xffffffffu, ls, 1);
            ls += __shfl_xor_sync(0xffffffffu, ls, 2);
            ls += __shfl_xor_sync(0xffffffffu, ls, 4);
            ls += __shfl_xor_sync(0xffffffffu, ls, 8);
            l_i[i] = l_i[i] * corr + ls;
            m_i[i] = m_new;
#pragma unroll
            for (int j = 0; j < 4; j++) acc[i][j] *= corr;
        }
        __syncwarp();   // P rows are produced/consumed by the same warp

        // acc += P @ V
#pragma unroll 8
        for (int c = 0; c < BC; c++) {
            float b[4], a[8];
#pragma unroll
            for (int j = 0; j < 4; j++) b[j] = Vsm[c * SROW + tx * 4 + j];
#pragma unroll
            for (int i = 0; i < 8; i++) a[i] = Psm[(ty * 8 + i) * SROW + c];
#pragma unroll
            for (int i = 0; i < 8; i++)
#pragma unroll
                for (int j = 0; j < 4; j++)
                    acc[i][j] += a[i] * b[j];
        }
    }

    // Epilogue: normalize and store
    float* Og = Ob + ((size_t)n * LSEQ + (size_t)qt * BR) * D_MODEL + h * HEAD_D;
#pragma unroll
    for (int i = 0; i < 8; i++) {
        float inv = 1.f / l_i[i];
        int row = ty * 8 + i;
#pragma unroll
        for (int j = 0; j < 4; j++)
            Og[(size_t)row * D_MODEL + tx * 4 + j] = acc[i][j] * inv;
    }
}

// ---------------------------------------------------------------------------
// kernel_launch: 3 projections -> flash attention -> output projection
// ---------------------------------------------------------------------------
extern "C" void kernel_launch(void* const* d_in, const int* in_sizes, int n_in,
                              void* d_out, int out_size)
{
    const float* queries = (const float*)d_in[0];
    const float* keys    = (const float*)d_in[1];
    const float* values  = (const float*)d_in[2];
    const float* Wq = (const float*)d_in[3];
    const float* bq = (const float*)d_in[4];
    const float* Wk = (const float*)d_in[5];
    const float* bk = (const float*)d_in[6];
    const float* Wv = (const float*)d_in[7];
    const float* bv = (const float*)d_in[8];
    const float* Wo = (const float*)d_in[9];
    const float* bo = (const float*)d_in[10];
    float* out = (float*)d_out;

    float *gq, *gk, *gv, *ga;
    cudaGetSymbolAddress((void**)&gq, g_q);
    cudaGetSymbolAddress((void**)&gk, g_k);
    cudaGetSymbolAddress((void**)&gv, g_v);
    cudaGetSymbolAddress((void**)&ga, g_attn);

    cudaFuncSetAttribute(flash_attn_kernel,
                         cudaFuncAttributeMaxDynamicSharedMemorySize, ATTN_SMEM);

    dim3 gBlk(256);
    dim3 gGrd(D_MODEL / BN, MTOT / BM);   // (8, 32)

    gemm_bias_kernel<<<gGrd, gBlk>>>(queries, Wq, bq, gq, MTOT, D_MODEL, D_MODEL);
    gemm_bias_kernel<<<gGrd, gBlk>>>(keys,    Wk, bk, gk, MTOT, D_MODEL, D_MODEL);
    gemm_bias_kernel<<<gGrd, gBlk>>>(values,  Wv, bv, gv, MTOT, D_MODEL, D_MODEL);

    dim3 aGrd(LSEQ / BR, N_HEADS, NB);    // (32, 16, 2)
    flash_attn_kernel<<<aGrd, 128, ATTN_SMEM>>>(gq, gk, gv, ga);

    gemm_bias_kernel<<<gGrd, gBlk>>>(ga, Wo, bo, out, MTOT, D_MODEL, D_MODEL);
}

// round 3
// speedup vs baseline: 1.2614x; 1.2614x over previous
#include <cuda_runtime.h>
#include <cuda_bf16.h>
#include <cstdint>
#include <math.h>

// Problem constants (fixed shapes from reference)
#define D_MODEL 1024
#define N_HEADS 16
#define HEAD_D  64
#define NB      2
#define LSEQ    2048
#define MTOT    (NB * LSEQ)   // 4096 rows total

// ---------------------------------------------------------------------------
// Scratch (allocation-free rule: __device__ globals)
// ---------------------------------------------------------------------------
__device__ float g_q[(size_t)MTOT * D_MODEL];
__device__ float g_k[(size_t)MTOT * D_MODEL];
__device__ float g_v[(size_t)MTOT * D_MODEL];
__device__ float g_attn[(size_t)MTOT * D_MODEL];

// bf16 hi/lo splits of GEMM operands
__device__ __nv_bfloat16 g_xh[3][(size_t)MTOT * D_MODEL];   // queries/keys/values hi
__device__ __nv_bfloat16 g_xl[3][(size_t)MTOT * D_MODEL];   // lo
__device__ __nv_bfloat16 g_wh[4][(size_t)D_MODEL * D_MODEL];// Wq/Wk/Wv/Wo hi
__device__ __nv_bfloat16 g_wl[4][(size_t)D_MODEL * D_MODEL];// lo
__device__ __nv_bfloat16 g_ah[(size_t)MTOT * D_MODEL];      // attn out hi
__device__ __nv_bfloat16 g_al[(size_t)MTOT * D_MODEL];      // attn out lo

// ---------------------------------------------------------------------------
// fp32 -> bf16 hi/lo split (elementwise), float4 per thread
// ---------------------------------------------------------------------------
__global__ __launch_bounds__(256)
void split_bf16_kernel(const float* __restrict__ src,
                       __nv_bfloat16* __restrict__ hi,
                       __nv_bfloat16* __restrict__ lo, int n4)
{
    int i = blockIdx.x * blockDim.x + threadIdx.x;
    if (i >= n4) return;
    float4 v = ((const float4*)src)[i];
    __nv_bfloat16 hx = __float2bfloat16_rn(v.x);
    __nv_bfloat16 hy = __float2bfloat16_rn(v.y);
    __nv_bfloat16 hz = __float2bfloat16_rn(v.z);
    __nv_bfloat16 hw = __float2bfloat16_rn(v.w);
    __nv_bfloat162 h01; h01.x = hx; h01.y = hy;
    __nv_bfloat162 h23; h23.x = hz; h23.y = hw;
    uint2 ho;
    ho.x = *reinterpret_cast<uint32_t*>(&h01);
    ho.y = *reinterpret_cast<uint32_t*>(&h23);
    ((uint2*)hi)[i] = ho;
    __nv_bfloat162 l01 = __floats2bfloat162_rn(v.x - __bfloat162float(hx),
                                               v.y - __bfloat162float(hy));
    __nv_bfloat162 l23 = __floats2bfloat162_rn(v.z - __bfloat162float(hz),
                                               v.w - __bfloat162float(hw));
    uint2 loo;
    loo.x = *reinterpret_cast<uint32_t*>(&l01);
    loo.y = *reinterpret_cast<uint32_t*>(&l23);
    ((uint2*)lo)[i] = loo;
}

// ---------------------------------------------------------------------------
// Tensor-core GEMM (mma.sync m16n8k16 bf16, fp32 emulated via hi/lo split):
//   C[m,n] = sum_k X[m,k] * W[n,k] + bias[n]
// Block tile 128x128, K chunk 32, 256 threads = 8 warps (2 x 4).
// Warp tile 64x32 -> 4 m-frags x 4 n-frags of m16n8k16.
// ---------------------------------------------------------------------------
#define ASTR 40   // smem row stride in bf16 elements (bank-conflict-free)

__device__ __forceinline__ void mma16816(float* c, const uint32_t* a, const uint32_t* b)
{
    asm volatile(
        "mma.sync.aligned.m16n8k16.row.col.f32.bf16.bf16.f32 "
        "{%0,%1,%2,%3}, {%4,%5,%6,%7}, {%8,%9}, {%0,%1,%2,%3};"
        : "+f"(c[0]), "+f"(c[1]), "+f"(c[2]), "+f"(c[3])
        : "r"(a[0]), "r"(a[1]), "r"(a[2]), "r"(a[3]), "r"(b[0]), "r"(b[1]));
}

__global__ __launch_bounds__(256, 1)
void gemm_mma_kernel(const __nv_bfloat16* __restrict__ Xh,
                     const __nv_bfloat16* __restrict__ Xl,
                     const __nv_bfloat16* __restrict__ Wh,
                     const __nv_bfloat16* __restrict__ Wl,
                     const float* __restrict__ bias, float* __restrict__ C)
{
    __shared__ __nv_bfloat16 Ah[128 * ASTR];
    __shared__ __nv_bfloat16 Al[128 * ASTR];
    __shared__ __nv_bfloat16 Bh[128 * ASTR];
    __shared__ __nv_bfloat16 Bl[128 * ASTR];

    const int tid    = threadIdx.x;
    const int lane   = tid & 31;
    const int wid    = tid >> 5;
    const int warp_m = wid >> 2;          // 0..1  (64 rows each)
    const int warp_n = wid & 3;           // 0..3  (32 cols each)
    const int bm     = blockIdx.y * 128;
    const int bn     = blockIdx.x * 128;

    const int lrow  = tid >> 1;           // 0..127 tile row to load
    const int lhalf = (tid & 1) * 16;     // k-subrange 0..15 / 16..31

    float acc[4][4][4];
#pragma unroll
    for (int mf = 0; mf < 4; mf++)
#pragma unroll
        for (int nf = 0; nf < 4; nf++)
#pragma unroll
            for (int r = 0; r < 4; r++) acc[mf][nf][r] = 0.f;

    const int r0 = lane >> 2;          // 0..7
    const int c0 = (lane & 3) * 2;     // 0,2,4,6

    for (int ch = 0; ch < D_MODEL / 32; ch++) {
        const int kofs = ch * 32;
        const size_t xoff = (size_t)(bm + lrow) * D_MODEL + kofs + lhalf;
        const size_t woff = (size_t)(bn + lrow) * D_MODEL + kofs + lhalf;

        // Prefetch gmem (2x uint4 = 16 bf16 per array per thread)
        uint4 vxh0 = *(const uint4*)(Xh + xoff);
        uint4 vxh1 = *(const uint4*)(Xh + xoff + 8);
        uint4 vxl0 = *(const uint4*)(Xl + xoff);
        uint4 vxl1 = *(const uint4*)(Xl + xoff + 8);
        uint4 vwh0 = *(const uint4*)(Wh + woff);
        uint4 vwh1 = *(const uint4*)(Wh + woff + 8);
        uint4 vwl0 = *(const uint4*)(Wl + woff);
        uint4 vwl1 = *(const uint4*)(Wl + woff + 8);

        __syncthreads();   // previous chunk's MMAs done reading smem
        {
            const int so = lrow * ASTR + lhalf;
            *(uint4*)(Ah + so)     = vxh0;
            *(uint4*)(Ah + so + 8) = vxh1;
            *(uint4*)(Al + so)     = vxl0;
            *(uint4*)(Al + so + 8) = vxl1;
            *(uint4*)(Bh + so)     = vwh0;
            *(uint4*)(Bh + so + 8) = vwh1;
            *(uint4*)(Bl + so)     = vwl0;
            *(uint4*)(Bl + so + 8) = vwl1;
        }
        __syncthreads();

#pragma unroll
        for (int kk = 0; kk < 32; kk += 16) {
            uint32_t ah[4][4], al[4][4];
#pragma unroll
            for (int mf = 0; mf < 4; mf++) {
                int mr = warp_m * 64 + mf * 16 + r0;
                ah[mf][0] = *(const uint32_t*)(Ah + mr * ASTR + kk + c0);
                ah[mf][1] = *(const uint32_t*)(Ah + (mr + 8) * ASTR + kk + c0);
                ah[mf][2] = *(const uint32_t*)(Ah + mr * ASTR + kk + c0 + 8);
                ah[mf][3] = *(const uint32_t*)(Ah + (mr + 8) * ASTR + kk + c0 + 8);
                al[mf][0] = *(const uint32_t*)(Al + mr * ASTR + kk + c0);
                al[mf][1] = *(const uint32_t*)(Al + (mr + 8) * ASTR + kk + c0);
                al[mf][2] = *(const uint32_t*)(Al + mr * ASTR + kk + c0 + 8);
                al[mf][3] = *(const uint32_t*)(Al + (mr + 8) * ASTR + kk + c0 + 8);
            }
            uint32_t bh[4][2], bl[4][2];
#pragma unroll
            for (int nf = 0; nf < 4; nf++) {
                int nr = warp_n * 32 + nf * 8 + r0;
                bh[nf][0] = *(const uint32_t*)(Bh + nr * ASTR + kk + c0);
                bh[nf][1] = *(const uint32_t*)(Bh + nr * ASTR + kk + c0 + 8);
                bl[nf][0] = *(const uint32_t*)(Bl + nr * ASTR + kk + c0);
                bl[nf][1] = *(const uint32_t*)(Bl + nr * ASTR + kk + c0 + 8);
            }
#pragma unroll
            for (int mf = 0; mf < 4; mf++)
#pragma unroll
                for (int nf = 0; nf < 4; nf++) {
                    mma16816(acc[mf][nf], ah[mf], bh[nf]);
                    mma16816(acc[mf][nf], ah[mf], bl[nf]);
                    mma16816(acc[mf][nf], al[mf], bh[nf]);
                }
        }
    }

    // Epilogue: bias + store (float2 per c-pair)
#pragma unroll
    for (int mf = 0; mf < 4; mf++) {
        int row = bm + warp_m * 64 + mf * 16 + r0;
#pragma unroll
        for (int nf = 0; nf < 4; nf++) {
            int col = bn + warp_n * 32 + nf * 8 + c0;
            float2 bv = *(const float2*)(bias + col);
            float2 o0, o1;
            o0.x = acc[mf][nf][0] + bv.x;
            o0.y = acc[mf][nf][1] + bv.y;
            o1.x = acc[mf][nf][2] + bv.x;
            o1.y = acc[mf][nf][3] + bv.y;
            *(float2*)(C + (size_t)row * D_MODEL + col)       = o0;
            *(float2*)(C + (size_t)(row + 8) * D_MODEL + col) = o1;
        }
    }
}

// ---------------------------------------------------------------------------
// Flash attention (causal), head dim 64. Vectorized smem (LDS.128 everywhere).
// Block: one 64-row Q tile of one (batch, head). 128 threads.
// Thread grid 16(tx: cols) x 8(ty: rows); microtile 8 rows x 4 cols.
// Smem stride 68 floats (16B-aligned microtile bases). P stored transposed.
// ---------------------------------------------------------------------------
#define BR 64
#define BC 64
#define SROW 68
#define ATTN_SMEM (4 * 64 * SROW * (int)sizeof(float))

__global__ __launch_bounds__(128, 2)
void flash_attn_kernel(const float* __restrict__ Qb, const float* __restrict__ Kb,
                       const float* __restrict__ Vb, float* __restrict__ Ob)
{
    extern __shared__ float smbuf[];
    float* Qts = smbuf;                        // Qts[d*SROW + r] = Q[r][d]
    float* Kts = smbuf + 64 * SROW;            // Kts[d*SROW + c] = K[c][d]
    float* Vsm = smbuf + 2 * 64 * SROW;        // Vsm[c*SROW + d] = V[c][d]
    float* Psm = smbuf + 3 * 64 * SROW;        // Psm[c*SROW + r] = P[r][c] (transposed)

    const int tid = threadIdx.x;
    const int tx  = tid & 15;   // 0..15
    const int ty  = tid >> 4;   // 0..7
    const int qt  = blockIdx.x;
    const int h   = blockIdx.y;
    const int n   = blockIdx.z;

    const float scale = 0.125f;  // 1/sqrt(64)

    // Load Q tile, transposed into smem (coalesced float4 gmem reads)
    const float* Qg = Qb + ((size_t)n * LSEQ + (size_t)qt * BR) * D_MODEL + h * HEAD_D;
#pragma unroll
    for (int i = 0; i < 8; i++) {
        int f   = tid + i * 128;     // 0..1023 float4 index
        int row = f >> 4;            // 0..63
        int c4  = (f & 15) << 2;     // 0..60
        float4 v = *(const float4*)(Qg + (size_t)row * D_MODEL + c4);
        Qts[(c4 + 0) * SROW + row] = v.x;
        Qts[(c4 + 1) * SROW + row] = v.y;
        Qts[(c4 + 2) * SROW + row] = v.z;
        Qts[(c4 + 3) * SROW + row] = v.w;
    }

    float m_i[8], l_i[8], acc[8][4];
#pragma unroll
    for (int i = 0; i < 8; i++) {
        m_i[i] = -INFINITY;
        l_i[i] = 0.f;
#pragma unroll
        for (int j = 0; j < 4; j++) acc[i][j] = 0.f;
    }

    for (int kt = 0; kt <= qt; kt++) {
        const float* Kg = Kb + ((size_t)n * LSEQ + (size_t)kt * BC) * D_MODEL + h * HEAD_D;
        const float* Vg = Vb + ((size_t)n * LSEQ + (size_t)kt * BC) * D_MODEL + h * HEAD_D;

        __syncthreads();   // previous iteration done reading K/V
#pragma unroll
        for (int i = 0; i < 8; i++) {
            int f   = tid + i * 128;
            int row = f >> 4;
            int c4  = (f & 15) << 2;
            float4 kv = *(const float4*)(Kg + (size_t)row * D_MODEL + c4);
            Kts[(c4 + 0) * SROW + row] = kv.x;
            Kts[(c4 + 1) * SROW + row] = kv.y;
            Kts[(c4 + 2) * SROW + row] = kv.z;
            Kts[(c4 + 3) * SROW + row] = kv.w;
            float4 vv = *(const float4*)(Vg + (size_t)row * D_MODEL + c4);
            *(float4*)(&Vsm[row * SROW + c4]) = vv;
        }
        __syncthreads();

        // Scores: sc[i][j] = Q[row] . K[col]  (LDS.128 operand fetches)
        float sc[8][4];
#pragma unroll
        for (int i = 0; i < 8; i++)
#pragma unroll
            for (int j = 0; j < 4; j++) sc[i][j] = 0.f;

#pragma unroll 4
        for (int d = 0; d < HEAD_D; d++) {
            float4 a0 = *(const float4*)(&Qts[d * SROW + ty * 8]);
            float4 a1 = *(const float4*)(&Qts[d * SROW + ty * 8 + 4]);
            float4 b0 = *(const float4*)(&Kts[d * SROW + tx * 4]);
            float a[8] = {a0.x, a0.y, a0.z, a0.w, a1.x, a1.y, a1.z, a1.w};
            float b[4] = {b0.x, b0.y, b0.z, b0.w};
#pragma unroll
            for (int i = 0; i < 8; i++)
#pragma unroll
                for (int j = 0; j < 4; j++)
                    sc[i][j] += a[i] * b[j];
        }

        // Scale + causal mask (diagonal tile only)
        if (kt == qt) {
#pragma unroll
            for (int i = 0; i < 8; i++) {
                int rl = ty * 8 + i;
#pragma unroll
                for (int j = 0; j < 4; j++) {
                    int cl = tx * 4 + j;
                    sc[i][j] = (cl > rl) ? -INFINITY : sc[i][j] * scale;
                }
            }
        } else {
#pragma unroll
            for (int i = 0; i < 8; i++)
#pragma unroll
                for (int j = 0; j < 4; j++) sc[i][j] *= scale;
        }

        // Online softmax update (row stats reduced over 16 lanes sharing ty)
        float p[8][4];
#pragma unroll
        for (int i = 0; i < 8; i++) {
            float mx = fmaxf(fmaxf(sc[i][0], sc[i][1]), fmaxf(sc[i][2], sc[i][3]));
            mx = fmaxf(mx, __shfl_xor_sync(0xffffffffu, mx, 1));
            mx = fmaxf(mx, __shfl_xor_sync(0xffffffffu, mx, 2));
            mx = fmaxf(mx, __shfl_xor_sync(0xffffffffu, mx, 4));
            mx = fmaxf(mx, __shfl_xor_sync(0xffffffffu, mx, 8));
            float m_new = fmaxf(m_i[i], mx);
            float corr  = __expf(m_i[i] - m_new);   // 0 on first tile (m_i=-inf)
            float ls = 0.f;
#pragma unroll
            for (int j = 0; j < 4; j++) {
                p[i][j] = __expf(sc[i][j] - m_new);  // masked -> exp(-inf)=0
                ls += p[i][j];
            }
            ls += __shfl_xor_sync(0xffffffffu, ls, 1);
            ls += __shfl_xor_sync(0xffffffffu, ls, 2);
            ls += __shfl_xor_sync(0xffffffffu, ls, 4);
            ls += __shfl_xor_sync(0xffffffffu, ls, 8);
            l_i[i] = l_i[i] * corr + ls;
            m_i[i] = m_new;
#pragma unroll
            for (int j = 0; j < 4; j++) acc[i][j] *= corr;
        }
        // Store P transposed: Psm[col][row], float4 over rows
#pragma unroll
        for (int j = 0; j < 4; j++) {
            int col = tx * 4 + j;
            float4 v0 = make_float4(p[0][j], p[1][j], p[2][j], p[3][j]);
            float4 v1 = make_float4(p[4][j], p[5][j], p[6][j], p[7][j]);
            *(float4*)(&Psm[col * SROW + ty * 8])     = v0;
            *(float4*)(&Psm[col * SROW + ty * 8 + 4]) = v1;
        }
        __syncwarp();   // P row-groups produced/consumed within the same warp

        // acc += P @ V   (all LDS.128)
#pragma unroll 4
        for (int c = 0; c < BC; c++) {
            float4 b0 = *(const float4*)(&Vsm[c * SROW + tx * 4]);
            float4 a0 = *(const float4*)(&Psm[c * SROW + ty * 8]);
            float4 a1 = *(const float4*)(&Psm[c * SROW + ty * 8 + 4]);
            float a[8] = {a0.x, a0.y, a0.z, a0.w, a1.x, a1.y, a1.z, a1.w};
            float b[4] = {b0.x, b0.y, b0.z, b0.w};
#pragma unroll
            for (int i = 0; i < 8; i++)
#pragma unroll
                for (int j = 0; j < 4; j++)
                    acc[i][j] += a[i] * b[j];
        }
    }

    // Epilogue: normalize and store
    float* Og = Ob + ((size_t)n * LSEQ + (size_t)qt * BR) * D_MODEL + h * HEAD_D;
#pragma unroll
    for (int i = 0; i < 8; i++) {
        float inv = 1.f / l_i[i];
        int row = ty * 8 + i;
        float4 o;
        o.x = acc[i][0] * inv; o.y = acc[i][1] * inv;
        o.z = acc[i][2] * inv; o.w = acc[i][3] * inv;
        *(float4*)(Og + (size_t)row * D_MODEL + tx * 4) = o;
    }
}

// ---------------------------------------------------------------------------
// kernel_launch: split -> 3 projections -> flash attention -> split -> out proj
// ---------------------------------------------------------------------------
extern "C" void kernel_launch(void* const* d_in, const int* in_sizes, int n_in,
                              void* d_out, int out_size)
{
    const float* queries = (const float*)d_in[0];
    const float* keys    = (const float*)d_in[1];
    const float* values  = (const float*)d_in[2];
    const float* Wq = (const float*)d_in[3];
    const float* bq = (const float*)d_in[4];
    const float* Wk = (const float*)d_in[5];
    const float* bk = (const float*)d_in[6];
    const float* Wv = (const float*)d_in[7];
    const float* bv = (const float*)d_in[8];
    const float* Wo = (const float*)d_in[9];
    const float* bo = (const float*)d_in[10];
    float* out = (float*)d_out;

    float *gq, *gk, *gv, *ga;
    cudaGetSymbolAddress((void**)&gq, g_q);
    cudaGetSymbolAddress((void**)&gk, g_k);
    cudaGetSymbolAddress((void**)&gv, g_v);
    cudaGetSymbolAddress((void**)&ga, g_attn);

    __nv_bfloat16 *xh, *xl, *wh, *wl, *ah, *al;
    cudaGetSymbolAddress((void**)&xh, g_xh);
    cudaGetSymbolAddress((void**)&xl, g_xl);
    cudaGetSymbolAddress((void**)&wh, g_wh);
    cudaGetSymbolAddress((void**)&wl, g_wl);
    cudaGetSymbolAddress((void**)&ah, g_ah);
    cudaGetSymbolAddress((void**)&al, g_al);

    const size_t XSZ = (size_t)MTOT * D_MODEL;     // 4M elements
    const size_t WSZ = (size_t)D_MODEL * D_MODEL;  // 1M elements
    const int XB = (int)(XSZ / 4 / 256);           // blocks for input split
    const int WB = (int)(WSZ / 4 / 256);

    cudaFuncSetAttribute(flash_attn_kernel,
                         cudaFuncAttributeMaxDynamicSharedMemorySize, ATTN_SMEM);

    // Split inputs and weights to bf16 hi/lo
    split_bf16_kernel<<<XB, 256>>>(queries, xh,           xl,           (int)(XSZ / 4));
    split_bf16_kernel<<<XB, 256>>>(keys,    xh + XSZ,     xl + XSZ,     (int)(XSZ / 4));
    split_bf16_kernel<<<XB, 256>>>(values,  xh + 2 * XSZ, xl + 2 * XSZ, (int)(XSZ / 4));
    split_bf16_kernel<<<WB, 256>>>(Wq, wh,           wl,           (int)(WSZ / 4));
    split_bf16_kernel<<<WB, 256>>>(Wk, wh + WSZ,     wl + WSZ,     (int)(WSZ / 4));
    split_bf16_kernel<<<WB, 256>>>(Wv, wh + 2 * WSZ, wl + 2 * WSZ, (int)(WSZ / 4));
    split_bf16_kernel<<<WB, 256>>>(Wo, wh + 3 * WSZ, wl + 3 * WSZ, (int)(WSZ / 4));

    dim3 gBlk(256);
    dim3 gGrd(D_MODEL / 128, MTOT / 128);   // (8, 32)

    gemm_mma_kernel<<<gGrd, gBlk>>>(xh,           xl,           wh,           wl,           bq, gq);
    gemm_mma_kernel<<<gGrd, gBlk>>>(xh + XSZ,     xl + XSZ,     wh + WSZ,     wl + WSZ,     bk, gk);
    gemm_mma_kernel<<<gGrd, gBlk>>>(xh + 2 * XSZ, xl + 2 * XSZ, wh + 2 * WSZ, wl + 2 * WSZ, bv, gv);

    dim3 aGrd(LSEQ / BR, N_HEADS, NB);      // (32, 16, 2)
    flash_attn_kernel<<<aGrd, 128, ATTN_SMEM>>>(gq, gk, gv, ga);

    split_bf16_kernel<<<XB, 256>>>(ga, ah, al, (int)(XSZ / 4));
    gemm_mma_kernel<<<gGrd, gBlk>>>(ah, al, wh + 3 * WSZ, wl + 3 * WSZ, bo, out);
}

// round 5
// speedup vs baseline: 1.8939x; 1.5014x over previous
#include <cuda_runtime.h>
#include <cuda_bf16.h>
#include <cstdint>
#include <math.h>

// Problem constants (fixed shapes from reference)
#define D_MODEL 1024
#define N_HEADS 16
#define HEAD_D  64
#define NB      2
#define LSEQ    2048
#define MTOT    (NB * LSEQ)   // 4096 rows total

// ---------------------------------------------------------------------------
// Scratch (allocation-free rule: __device__ globals) — all bf16 hi/lo pairs
// ---------------------------------------------------------------------------
__device__ __nv_bfloat16 g_xh[3][(size_t)MTOT * D_MODEL];   // q/k/v inputs hi
__device__ __nv_bfloat16 g_xl[3][(size_t)MTOT * D_MODEL];   // lo
__device__ __nv_bfloat16 g_wh[4][(size_t)D_MODEL * D_MODEL];// Wq/Wk/Wv/Wo hi
__device__ __nv_bfloat16 g_wl[4][(size_t)D_MODEL * D_MODEL];// lo
__device__ __nv_bfloat16 g_qh[(size_t)MTOT * D_MODEL];      // projected Q hi/lo
__device__ __nv_bfloat16 g_ql[(size_t)MTOT * D_MODEL];
__device__ __nv_bfloat16 g_kh[(size_t)MTOT * D_MODEL];
__device__ __nv_bfloat16 g_kl[(size_t)MTOT * D_MODEL];
__device__ __nv_bfloat16 g_vh[(size_t)MTOT * D_MODEL];
__device__ __nv_bfloat16 g_vl[(size_t)MTOT * D_MODEL];
__device__ __nv_bfloat16 g_ah[(size_t)MTOT * D_MODEL];      // attn out hi/lo
__device__ __nv_bfloat16 g_al[(size_t)MTOT * D_MODEL];

// ---------------------------------------------------------------------------
// Small helpers
// ---------------------------------------------------------------------------
__device__ __forceinline__ uint32_t smem_u32(const void* p) {
    uint32_t a;
    asm("{ .reg .u64 t; cvta.to.shared.u64 t, %1; cvt.u32.u64 %0, t; }"
        : "=r"(a) : "l"(p));
    return a;
}
__device__ __forceinline__ void split2(float x, float y, uint32_t& hi, uint32_t& lo) {
    __nv_bfloat16 hx = __float2bfloat16_rn(x), hy = __float2bfloat16_rn(y);
    __nv_bfloat162 hp; hp.x = hx; hp.y = hy;
    hi = *reinterpret_cast<uint32_t*>(&hp);
    __nv_bfloat162 lp = __floats2bfloat162_rn(x - __bfloat162float(hx),
                                              y - __bfloat162float(hy));
    lo = *reinterpret_cast<uint32_t*>(&lp);
}
__device__ __forceinline__ void mma16816(float* c, const uint32_t* a, const uint32_t* b) {
    asm volatile(
        "mma.sync.aligned.m16n8k16.row.col.f32.bf16.bf16.f32 "
        "{%0,%1,%2,%3}, {%4,%5,%6,%7}, {%8,%9}, {%0,%1,%2,%3};"
        : "+f"(c[0]), "+f"(c[1]), "+f"(c[2]), "+f"(c[3])
        : "r"(a[0]), "r"(a[1]), "r"(a[2]), "r"(a[3]), "r"(b[0]), "r"(b[1]));
}
__device__ __forceinline__ void ldsm_x4(uint32_t* r, uint32_t a) {
    asm volatile("ldmatrix.sync.aligned.m8n8.x4.shared.b16 {%0,%1,%2,%3},[%4];"
                 : "=r"(r[0]), "=r"(r[1]), "=r"(r[2]), "=r"(r[3]) : "r"(a));
}
__device__ __forceinline__ void ldsm_x2(uint32_t* r, uint32_t a) {
    asm volatile("ldmatrix.sync.aligned.m8n8.x2.shared.b16 {%0,%1},[%2];"
                 : "=r"(r[0]), "=r"(r[1]) : "r"(a));
}
__device__ __forceinline__ void ldsm_x2t(uint32_t* r, uint32_t a) {
    asm volatile("ldmatrix.sync.aligned.m8n8.x2.trans.shared.b16 {%0,%1},[%2];"
                 : "=r"(r[0]), "=r"(r[1]) : "r"(a));
}

// ---------------------------------------------------------------------------
// fp32 -> bf16 hi/lo split (elementwise), float4 per thread
// ---------------------------------------------------------------------------
__global__ __launch_bounds__(256)
void split_bf16_kernel(const float* __restrict__ src,
                       __nv_bfloat16* __restrict__ hi,
                       __nv_bfloat16* __restrict__ lo, int n4)
{
    int i = blockIdx.x * blockDim.x + threadIdx.x;
    if (i >= n4) return;
    float4 v = ((const float4*)src)[i];
    uint32_t h0, l0, h1, l1;
    split2(v.x, v.y, h0, l0);
    split2(v.z, v.w, h1, l1);
    ((uint2*)hi)[i] = make_uint2(h0, h1);
    ((uint2*)lo)[i] = make_uint2(l0, l1);
}

// ---------------------------------------------------------------------------
// Tensor-core GEMM (mma.sync m16n8k16 bf16, fp32 emulated via hi/lo split):
//   C[m,n] = sum_k X[m,k] * W[n,k] + bias[n]
// Block tile 128x128, K chunk 32, 256 threads = 8 warps (2 x 4).
// OM=0: fp32 out to Cf.  OM=1: bf16 hi/lo out to Ch/Cl.
// ---------------------------------------------------------------------------
#define ASTR 40   // smem row stride in bf16 elements (bank-conflict-free)

template <int OM>
__global__ __launch_bounds__(256, 1)
void gemm_mma_kernel(const __nv_bfloat16* __restrict__ Xh,
                     const __nv_bfloat16* __restrict__ Xl,
                     const __nv_bfloat16* __restrict__ Wh,
                     const __nv_bfloat16* __restrict__ Wl,
                     const float* __restrict__ bias, float* __restrict__ Cf,
                     __nv_bfloat16* __restrict__ Ch, __nv_bfloat16* __restrict__ Cl)
{
    __shared__ __nv_bfloat16 Ah[128 * ASTR];
    __shared__ __nv_bfloat16 Al[128 * ASTR];
    __shared__ __nv_bfloat16 Bh[128 * ASTR];
    __shared__ __nv_bfloat16 Bl[128 * ASTR];

    const int tid    = threadIdx.x;
    const int lane   = tid & 31;
    const int wid    = tid >> 5;
    const int warp_m = wid >> 2;          // 0..1  (64 rows each)
    const int warp_n = wid & 3;           // 0..3  (32 cols each)
    const int bm     = blockIdx.y * 128;
    const int bn     = blockIdx.x * 128;

    const int lrow  = tid >> 1;           // 0..127 tile row to load
    const int lhalf = (tid & 1) * 16;     // k-subrange 0..15 / 16..31

    float acc[4][4][4];
#pragma unroll
    for (int mf = 0; mf < 4; mf++)
#pragma unroll
        for (int nf = 0; nf < 4; nf++)
#pragma unroll
            for (int r = 0; r < 4; r++) acc[mf][nf][r] = 0.f;

    const int r0 = lane >> 2;          // 0..7
    const int c0 = (lane & 3) * 2;     // 0,2,4,6

    for (int ch = 0; ch < D_MODEL / 32; ch++) {
        const int kofs = ch * 32;
        const size_t xoff = (size_t)(bm + lrow) * D_MODEL + kofs + lhalf;
        const size_t woff = (size_t)(bn + lrow) * D_MODEL + kofs + lhalf;

        uint4 vxh0 = *(const uint4*)(Xh + xoff);
        uint4 vxh1 = *(const uint4*)(Xh + xoff + 8);
        uint4 vxl0 = *(const uint4*)(Xl + xoff);
        uint4 vxl1 = *(const uint4*)(Xl + xoff + 8);
        uint4 vwh0 = *(const uint4*)(Wh + woff);
        uint4 vwh1 = *(const uint4*)(Wh + woff + 8);
        uint4 vwl0 = *(const uint4*)(Wl + woff);
        uint4 vwl1 = *(const uint4*)(Wl + woff + 8);

        __syncthreads();
        {
            const int so = lrow * ASTR + lhalf;
            *(uint4*)(Ah + so)     = vxh0;
            *(uint4*)(Ah + so + 8) = vxh1;
            *(uint4*)(Al + so)     = vxl0;
            *(uint4*)(Al + so + 8) = vxl1;
            *(uint4*)(Bh + so)     = vwh0;
            *(uint4*)(Bh + so + 8) = vwh1;
            *(uint4*)(Bl + so)     = vwl0;
            *(uint4*)(Bl + so + 8) = vwl1;
        }
        __syncthreads();

#pragma unroll
        for (int kk = 0; kk < 32; kk += 16) {
            uint32_t ah[4][4], al[4][4];
#pragma unroll
            for (int mf = 0; mf < 4; mf++) {
                int mr = warp_m * 64 + mf * 16 + r0;
                ah[mf][0] = *(const uint32_t*)(Ah + mr * ASTR + kk + c0);
                ah[mf][1] = *(const uint32_t*)(Ah + (mr + 8) * ASTR + kk + c0);
                ah[mf][2] = *(const uint32_t*)(Ah + mr * ASTR + kk + c0 + 8);
                ah[mf][3] = *(const uint32_t*)(Ah + (mr + 8) * ASTR + kk + c0 + 8);
                al[mf][0] = *(const uint32_t*)(Al + mr * ASTR + kk + c0);
                al[mf][1] = *(const uint32_t*)(Al + (mr + 8) * ASTR + kk + c0);
                al[mf][2] = *(const uint32_t*)(Al + mr * ASTR + kk + c0 + 8);
                al[mf][3] = *(const uint32_t*)(Al + (mr + 8) * ASTR + kk + c0 + 8);
            }
            uint32_t bh[4][2], bl[4][2];
#pragma unroll
            for (int nf = 0; nf < 4; nf++) {
                int nr = warp_n * 32 + nf * 8 + r0;
                bh[nf][0] = *(const uint32_t*)(Bh + nr * ASTR + kk + c0);
                bh[nf][1] = *(const uint32_t*)(Bh + nr * ASTR + kk + c0 + 8);
                bl[nf][0] = *(const uint32_t*)(Bl + nr * ASTR + kk + c0);
                bl[nf][1] = *(const uint32_t*)(Bl + nr * ASTR + kk + c0 + 8);
            }
#pragma unroll
            for (int mf = 0; mf < 4; mf++)
#pragma unroll
                for (int nf = 0; nf < 4; nf++) {
                    mma16816(acc[mf][nf], ah[mf], bh[nf]);
                    mma16816(acc[mf][nf], ah[mf], bl[nf]);
                    mma16816(acc[mf][nf], al[mf], bh[nf]);
                }
        }
    }

    // Epilogue
#pragma unroll
    for (int mf = 0; mf < 4; mf++) {
        int row = bm + warp_m * 64 + mf * 16 + r0;
#pragma unroll
        for (int nf = 0; nf < 4; nf++) {
            int col = bn + warp_n * 32 + nf * 8 + c0;
            float2 bv = *(const float2*)(bias + col);
            float s00 = acc[mf][nf][0] + bv.x;
            float s01 = acc[mf][nf][1] + bv.y;
            float s10 = acc[mf][nf][2] + bv.x;
            float s11 = acc[mf][nf][3] + bv.y;
            if (OM == 0) {
                *(float2*)(Cf + (size_t)row * D_MODEL + col)       = make_float2(s00, s01);
                *(float2*)(Cf + (size_t)(row + 8) * D_MODEL + col) = make_float2(s10, s11);
            } else {
                uint32_t h0, l0, h1, l1;
                split2(s00, s01, h0, l0);
                split2(s10, s11, h1, l1);
                *(uint32_t*)(Ch + (size_t)row * D_MODEL + col)       = h0;
                *(uint32_t*)(Cl + (size_t)row * D_MODEL + col)       = l0;
                *(uint32_t*)(Ch + (size_t)(row + 8) * D_MODEL + col) = h1;
                *(uint32_t*)(Cl + (size_t)(row + 8) * D_MODEL + col) = l1;
            }
        }
    }
}

// ---------------------------------------------------------------------------
// Flash attention (causal) on tensor cores, bf16 hi/lo emulated fp32.
// Block: 64 Q rows of one (n, h). 128 threads = 4 warps, each warp 16 rows.
// QK^T: A=Q (ldmatrix.x4), B=K natural [s][d] layout (ldmatrix.x2).
// PV:   A=P from accumulators (register repack), B=V via ldmatrix.x2.trans.
// Outputs bf16 hi/lo for the final projection.
// ---------------------------------------------------------------------------
#define FA_STR 72                   // [64][72] bf16 tiles, conflict-free ldmatrix
#define FA_TILE (64 * FA_STR)
#define FA_SMEM (6 * FA_TILE * 2)   // 55296 B

__global__ __launch_bounds__(128, 2)
void flash_mma_kernel(const __nv_bfloat16* __restrict__ Qh_g, const __nv_bfloat16* __restrict__ Ql_g,
                      const __nv_bfloat16* __restrict__ Kh_g, const __nv_bfloat16* __restrict__ Kl_g,
                      const __nv_bfloat16* __restrict__ Vh_g, const __nv_bfloat16* __restrict__ Vl_g,
                      __nv_bfloat16* __restrict__ Oh_g, __nv_bfloat16* __restrict__ Ol_g)
{
    extern __shared__ __nv_bfloat16 fsm[];
    __nv_bfloat16* sQh = fsm;
    __nv_bfloat16* sQl = fsm + FA_TILE;
    __nv_bfloat16* sKh = fsm + 2 * FA_TILE;
    __nv_bfloat16* sKl = fsm + 3 * FA_TILE;
    __nv_bfloat16* sVh = fsm + 4 * FA_TILE;
    __nv_bfloat16* sVl = fsm + 5 * FA_TILE;

    const int tid  = threadIdx.x;
    const int lane = tid & 31;
    const int wid  = tid >> 5;
    const int qt   = blockIdx.x;
    const int h    = blockIdx.y;
    const int n    = blockIdx.z;

    const uint32_t uQh = smem_u32(sQh);
    const uint32_t uQl = smem_u32(sQl);
    const uint32_t uKh = smem_u32(sKh);
    const uint32_t uKl = smem_u32(sKl);
    const uint32_t uVh = smem_u32(sVh);
    const uint32_t uVl = smem_u32(sVl);

    const float scale = 0.125f;   // 1/sqrt(64)
    const int wr = wid * 16;      // warp's Q-row base within tile
    const int r0 = lane >> 2;     // 0..7
    const int c0 = (lane & 3) * 2;

    // Load Q tile (hi/lo), natural [row][d] layout.
    // 64 rows x 64 bf16 = 64 rows x 8 uint4 chunks = 512 vector loads.
    const size_t qrow0 = (size_t)(n * LSEQ + qt * 64);
    const size_t gq = qrow0 * D_MODEL + (size_t)h * HEAD_D;
#pragma unroll
    for (int i = 0; i < 4; i++) {
        int f = tid + i * 128;          // 0..511
        int row = f >> 3, c8 = (f & 7) * 8;
        int so = row * FA_STR + c8;
        size_t go = gq + (size_t)row * D_MODEL + c8;
        *(uint4*)(sQh + so) = *(const uint4*)(Qh_g + go);
        *(uint4*)(sQl + so) = *(const uint4*)(Ql_g + go);
    }

    float oacc[8][4];
#pragma unroll
    for (int nf = 0; nf < 8; nf++)
#pragma unroll
        for (int j = 0; j < 4; j++) oacc[nf][j] = 0.f;
    float m0 = -INFINITY, m1 = -INFINITY, l0 = 0.f, l1 = 0.f;

    for (int kt = 0; kt <= qt; kt++) {
        __syncthreads();   // previous iter done reading smem (also orders Q on iter 0)
        const size_t gk = ((size_t)(n * LSEQ + kt * 64)) * D_MODEL + (size_t)h * HEAD_D;
#pragma unroll
        for (int i = 0; i < 4; i++) {
            int f = tid + i * 128;      // 0..511
            int row = f >> 3, c8 = (f & 7) * 8;
            int so = row * FA_STR + c8;
            size_t go = gk + (size_t)row * D_MODEL + c8;
            *(uint4*)(sKh + so) = *(const uint4*)(Kh_g + go);
            *(uint4*)(sKl + so) = *(const uint4*)(Kl_g + go);
            *(uint4*)(sVh + so) = *(const uint4*)(Vh_g + go);
            *(uint4*)(sVl + so) = *(const uint4*)(Vl_g + go);
        }
        __syncthreads();

        // ---- S = Q K^T (hi/lo 3-product) ----
        float sacc[8][4];
#pragma unroll
        for (int nf = 0; nf < 8; nf++)
#pragma unroll
            for (int j = 0; j < 4; j++) sacc[nf][j] = 0.f;

#pragma unroll
        for (int kc = 0; kc < 4; kc++) {
            const uint32_t aoff = (uint32_t)(((wr + (lane & 15)) * FA_STR
                                  + kc * 16 + (lane >> 4) * 8) * 2);
            uint32_t aqh[4], aql[4];
            ldsm_x4(aqh, uQh + aoff);
            ldsm_x4(aql, uQl + aoff);
            const uint32_t brow = (lane & 7);
            const uint32_t bk8  = ((lane >> 3) & 1) * 8;
#pragma unroll
            for (int nf = 0; nf < 8; nf++) {
                const uint32_t boff = (uint32_t)(((nf * 8 + brow) * FA_STR
                                      + kc * 16 + bk8) * 2);
                uint32_t bkh[2], bkl[2];
                ldsm_x2(bkh, uKh + boff);
                ldsm_x2(bkl, uKl + boff);
                mma16816(sacc[nf], aqh, bkh);
                mma16816(sacc[nf], aqh, bkl);
                mma16816(sacc[nf], aql, bkh);
            }
        }

        // ---- scale + causal mask ----
        if (kt == qt) {
#pragma unroll
            for (int nf = 0; nf < 8; nf++) {
                int col = nf * 8 + c0;
                int lrA = wr + r0, lrB = wr + r0 + 8;
                sacc[nf][0] = (col     > lrA) ? -INFINITY : sacc[nf][0] * scale;
                sacc[nf][1] = (col + 1 > lrA) ? -INFINITY : sacc[nf][1] * scale;
                sacc[nf][2] = (col     > lrB) ? -INFINITY : sacc[nf][2] * scale;
                sacc[nf][3] = (col + 1 > lrB) ? -INFINITY : sacc[nf][3] * scale;
            }
        } else {
#pragma unroll
            for (int nf = 0; nf < 8; nf++)
#pragma unroll
                for (int j = 0; j < 4; j++) sacc[nf][j] *= scale;
        }

        // ---- online softmax ----
        float mx0 = -INFINITY, mx1 = -INFINITY;
#pragma unroll
        for (int nf = 0; nf < 8; nf++) {
            mx0 = fmaxf(mx0, fmaxf(sacc[nf][0], sacc[nf][1]));
            mx1 = fmaxf(mx1, fmaxf(sacc[nf][2], sacc[nf][3]));
        }
        mx0 = fmaxf(mx0, __shfl_xor_sync(0xffffffffu, mx0, 1));
        mx0 = fmaxf(mx0, __shfl_xor_sync(0xffffffffu, mx0, 2));
        mx1 = fmaxf(mx1, __shfl_xor_sync(0xffffffffu, mx1, 1));
        mx1 = fmaxf(mx1, __shfl_xor_sync(0xffffffffu, mx1, 2));
        float mn0 = fmaxf(m0, mx0), mn1 = fmaxf(m1, mx1);
        float corr0 = __expf(m0 - mn0), corr1 = __expf(m1 - mn1);
        m0 = mn0; m1 = mn1;
        float rs0 = 0.f, rs1 = 0.f;
#pragma unroll
        for (int nf = 0; nf < 8; nf++) {
            sacc[nf][0] = __expf(sacc[nf][0] - m0);
            sacc[nf][1] = __expf(sacc[nf][1] - m0);
            sacc[nf][2] = __expf(sacc[nf][2] - m1);
            sacc[nf][3] = __expf(sacc[nf][3] - m1);
            rs0 += sacc[nf][0] + sacc[nf][1];
            rs1 += sacc[nf][2] + sacc[nf][3];
        }
        rs0 += __shfl_xor_sync(0xffffffffu, rs0, 1);
        rs0 += __shfl_xor_sync(0xffffffffu, rs0, 2);
        rs1 += __shfl_xor_sync(0xffffffffu, rs1, 1);
        rs1 += __shfl_xor_sync(0xffffffffu, rs1, 2);
        l0 = l0 * corr0 + rs0;
        l1 = l1 * corr1 + rs1;
#pragma unroll
        for (int nf = 0; nf < 8; nf++) {
            oacc[nf][0] *= corr0; oacc[nf][1] *= corr0;
            oacc[nf][2] *= corr1; oacc[nf][3] *= corr1;
        }

        // ---- O += P V (hi/lo 3-product, P repacked from accumulators) ----
#pragma unroll
        for (int kc = 0; kc < 4; kc++) {
            uint32_t aph[4], apl[4];
            split2(sacc[2 * kc][0],     sacc[2 * kc][1],     aph[0], apl[0]);
            split2(sacc[2 * kc][2],     sacc[2 * kc][3],     aph[1], apl[1]);
            split2(sacc[2 * kc + 1][0], sacc[2 * kc + 1][1], aph[2], apl[2]);
            split2(sacc[2 * kc + 1][2], sacc[2 * kc + 1][3], aph[3], apl[3]);
            const uint32_t vrow = (uint32_t)(kc * 16 + (lane & 15));
#pragma unroll
            for (int nf = 0; nf < 8; nf++) {
                const uint32_t voff = (uint32_t)((vrow * FA_STR + nf * 8) * 2);
                uint32_t bvh[2], bvl[2];
                ldsm_x2t(bvh, uVh + voff);
                ldsm_x2t(bvl, uVl + voff);
                mma16816(oacc[nf], aph, bvh);
                mma16816(oacc[nf], aph, bvl);
                mma16816(oacc[nf], apl, bvh);
            }
        }
    }

    // ---- epilogue: normalize, split to bf16 hi/lo, store ----
    float inv0 = 1.f / l0, inv1 = 1.f / l1;
    const size_t goA = (qrow0 + wr + r0) * D_MODEL + (size_t)h * HEAD_D;
    const size_t goB = goA + 8 * D_MODEL;
#pragma unroll
    for (int nf = 0; nf < 8; nf++) {
        int d = nf * 8 + c0;
        uint32_t h0, lo0, h1, lo1;
        split2(oacc[nf][0] * inv0, oacc[nf][1] * inv0, h0, lo0);
        split2(oacc[nf][2] * inv1, oacc[nf][3] * inv1, h1, lo1);
        *(uint32_t*)(Oh_g + goA + d) = h0;
        *(uint32_t*)(Ol_g + goA + d) = lo0;
        *(uint32_t*)(Oh_g + goB + d) = h1;
        *(uint32_t*)(Ol_g + goB + d) = lo1;
    }
}

// ---------------------------------------------------------------------------
// kernel_launch
// ---------------------------------------------------------------------------
extern "C" void kernel_launch(void* const* d_in, const int* in_sizes, int n_in,
                              void* d_out, int out_size)
{
    const float* queries = (const float*)d_in[0];
    const float* keys    = (const float*)d_in[1];
    const float* values  = (const float*)d_in[2];
    const float* Wq = (const float*)d_in[3];
    const float* bq = (const float*)d_in[4];
    const float* Wk = (const float*)d_in[5];
    const float* bk = (const float*)d_in[6];
    const float* Wv = (const float*)d_in[7];
    const float* bv = (const float*)d_in[8];
    const float* Wo = (const float*)d_in[9];
    const float* bo = (const float*)d_in[10];
    float* out = (float*)d_out;

    __nv_bfloat16 *xh, *xl, *wh, *wl, *qh, *ql, *kh, *kl, *vh, *vl, *ah, *al;
    cudaGetSymbolAddress((void**)&xh, g_xh);
    cudaGetSymbolAddress((void**)&xl, g_xl);
    cudaGetSymbolAddress((void**)&wh, g_wh);
    cudaGetSymbolAddress((void**)&wl, g_wl);
    cudaGetSymbolAddress((void**)&qh, g_qh);
    cudaGetSymbolAddress((void**)&ql, g_ql);
    cudaGetSymbolAddress((void**)&kh, g_kh);
    cudaGetSymbolAddress((void**)&kl, g_kl);
    cudaGetSymbolAddress((void**)&vh, g_vh);
    cudaGetSymbolAddress((void**)&vl, g_vl);
    cudaGetSymbolAddress((void**)&ah, g_ah);
    cudaGetSymbolAddress((void**)&al, g_al);

    const size_t XSZ = (size_t)MTOT * D_MODEL;     // 4M elements
    const size_t WSZ = (size_t)D_MODEL * D_MODEL;  // 1M elements
    const int XB = (int)(XSZ / 4 / 256);
    const int WB = (int)(WSZ / 4 / 256);

    cudaFuncSetAttribute(flash_mma_kernel,
                         cudaFuncAttributeMaxDynamicSharedMemorySize, FA_SMEM);

    // Split inputs and weights to bf16 hi/lo
    split_bf16_kernel<<<XB, 256>>>(queries, xh,           xl,           (int)(XSZ / 4));
    split_bf16_kernel<<<XB, 256>>>(keys,    xh + XSZ,     xl + XSZ,     (int)(XSZ / 4));
    split_bf16_kernel<<<XB, 256>>>(values,  xh + 2 * XSZ, xl + 2 * XSZ, (int)(XSZ / 4));
    split_bf16_kernel<<<WB, 256>>>(Wq, wh,           wl,           (int)(WSZ / 4));
    split_bf16_kernel<<<WB, 256>>>(Wk, wh + WSZ,     wl + WSZ,     (int)(WSZ / 4));
    split_bf16_kernel<<<WB, 256>>>(Wv, wh + 2 * WSZ, wl + 2 * WSZ, (int)(WSZ / 4));
    split_bf16_kernel<<<WB, 256>>>(Wo, wh + 3 * WSZ, wl + 3 * WSZ, (int)(WSZ / 4));

    dim3 gBlk(256);
    dim3 gGrd(D_MODEL / 128, MTOT / 128);   // (8, 32)

    // Projections: emit bf16 hi/lo directly
    gemm_mma_kernel<1><<<gGrd, gBlk>>>(xh,           xl,           wh,           wl,           bq, nullptr, qh, ql);
    gemm_mma_kernel<1><<<gGrd, gBlk>>>(xh + XSZ,     xl + XSZ,     wh + WSZ,     wl + WSZ,     bk, nullptr, kh, kl);
    gemm_mma_kernel<1><<<gGrd, gBlk>>>(xh + 2 * XSZ, xl + 2 * XSZ, wh + 2 * WSZ, wl + 2 * WSZ, bv, nullptr, vh, vl);

    // Attention on tensor cores, emits hi/lo
    dim3 aGrd(LSEQ / 64, N_HEADS, NB);      // (32, 16, 2)
    flash_mma_kernel<<<aGrd, 128, FA_SMEM>>>(qh, ql, kh, kl, vh, vl, ah, al);

    // Output projection: fp32 out
    gemm_mma_kernel<0><<<gGrd, gBlk>>>(ah, al, wh + 3 * WSZ, wl + 3 * WSZ, bo, out, nullptr, nullptr);
}

// round 6
// speedup vs baseline: 2.3908x; 1.2624x over previous
#include <cuda_runtime.h>
#include <cuda_bf16.h>
#include <cstdint>
#include <math.h>

// Problem constants (fixed shapes from reference)
#define D_MODEL 1024
#define N_HEADS 16
#define HEAD_D  64
#define NB      2
#define LSEQ    2048
#define MTOT    (NB * LSEQ)   // 4096 rows total

// ---------------------------------------------------------------------------
// Scratch (allocation-free rule: __device__ globals) — all bf16 hi/lo pairs
// ---------------------------------------------------------------------------
__device__ __nv_bfloat16 g_xh[3][(size_t)MTOT * D_MODEL];   // q/k/v inputs hi
__device__ __nv_bfloat16 g_xl[3][(size_t)MTOT * D_MODEL];   // lo
__device__ __nv_bfloat16 g_wh[4][(size_t)D_MODEL * D_MODEL];// Wq/Wk/Wv/Wo hi
__device__ __nv_bfloat16 g_wl[4][(size_t)D_MODEL * D_MODEL];// lo
__device__ __nv_bfloat16 g_qh[(size_t)MTOT * D_MODEL];      // projected Q hi/lo
__device__ __nv_bfloat16 g_ql[(size_t)MTOT * D_MODEL];
__device__ __nv_bfloat16 g_kh[(size_t)MTOT * D_MODEL];
__device__ __nv_bfloat16 g_kl[(size_t)MTOT * D_MODEL];
__device__ __nv_bfloat16 g_vh[(size_t)MTOT * D_MODEL];
__device__ __nv_bfloat16 g_vl[(size_t)MTOT * D_MODEL];
__device__ __nv_bfloat16 g_ah[(size_t)MTOT * D_MODEL];      // attn out hi/lo
__device__ __nv_bfloat16 g_al[(size_t)MTOT * D_MODEL];

// ---------------------------------------------------------------------------
// Small helpers
// ---------------------------------------------------------------------------
__device__ __forceinline__ uint32_t smem_u32(const void* p) {
    uint32_t a;
    asm("{ .reg .u64 t; cvta.to.shared.u64 t, %1; cvt.u32.u64 %0, t; }"
        : "=r"(a) : "l"(p));
    return a;
}
__device__ __forceinline__ void split2(float x, float y, uint32_t& hi, uint32_t& lo) {
    __nv_bfloat16 hx = __float2bfloat16_rn(x), hy = __float2bfloat16_rn(y);
    __nv_bfloat162 hp; hp.x = hx; hp.y = hy;
    hi = *reinterpret_cast<uint32_t*>(&hp);
    __nv_bfloat162 lp = __floats2bfloat162_rn(x - __bfloat162float(hx),
                                              y - __bfloat162float(hy));
    lo = *reinterpret_cast<uint32_t*>(&lp);
}
__device__ __forceinline__ void mma16816(float* c, const uint32_t* a, const uint32_t* b) {
    asm volatile(
        "mma.sync.aligned.m16n8k16.row.col.f32.bf16.bf16.f32 "
        "{%0,%1,%2,%3}, {%4,%5,%6,%7}, {%8,%9}, {%0,%1,%2,%3};"
        : "+f"(c[0]), "+f"(c[1]), "+f"(c[2]), "+f"(c[3])
        : "r"(a[0]), "r"(a[1]), "r"(a[2]), "r"(a[3]), "r"(b[0]), "r"(b[1]));
}
__device__ __forceinline__ void ldsm_x4(uint32_t* r, uint32_t a) {
    asm volatile("ldmatrix.sync.aligned.m8n8.x4.shared.b16 {%0,%1,%2,%3},[%4];"
                 : "=r"(r[0]), "=r"(r[1]), "=r"(r[2]), "=r"(r[3]) : "r"(a));
}
__device__ __forceinline__ void ldsm_x2(uint32_t* r, uint32_t a) {
    asm volatile("ldmatrix.sync.aligned.m8n8.x2.shared.b16 {%0,%1},[%2];"
                 : "=r"(r[0]), "=r"(r[1]) : "r"(a));
}
__device__ __forceinline__ void ldsm_x2t(uint32_t* r, uint32_t a) {
    asm volatile("ldmatrix.sync.aligned.m8n8.x2.trans.shared.b16 {%0,%1},[%2];"
                 : "=r"(r[0]), "=r"(r[1]) : "r"(a));
}
#define CP16(dst, src) \
    asm volatile("cp.async.cg.shared.global [%0], [%1], 16;" \
                 :: "r"(dst), "l"(src) : "memory")
#define CP_COMMIT() asm volatile("cp.async.commit_group;" ::: "memory")
#define CP_WAIT(n)  asm volatile("cp.async.wait_group %0;" :: "n"(n) : "memory")

// ---------------------------------------------------------------------------
// fp32 -> bf16 hi/lo split (elementwise), float4 per thread
// ---------------------------------------------------------------------------
__global__ __launch_bounds__(256)
void split_bf16_kernel(const float* __restrict__ src,
                       __nv_bfloat16* __restrict__ hi,
                       __nv_bfloat16* __restrict__ lo, int n4)
{
    int i = blockIdx.x * blockDim.x + threadIdx.x;
    if (i >= n4) return;
    float4 v = ((const float4*)src)[i];
    uint32_t h0, l0, h1, l1;
    split2(v.x, v.y, h0, l0);
    split2(v.z, v.w, h1, l1);
    ((uint2*)hi)[i] = make_uint2(h0, h1);
    ((uint2*)lo)[i] = make_uint2(l0, l1);
}

// ---------------------------------------------------------------------------
// Tensor-core GEMM (mma.sync m16n8k16 bf16, fp32 emulated via hi/lo split):
//   C[m,n] = sum_k X[m,k] * W[n,k] + bias[n]
// Block tile 128x128, K chunk 32, 256 threads = 8 warps (2 x 4).
// 2-stage cp.async pipeline; ldmatrix fragment loads.
// OM=0: fp32 out to Cf.  OM=1: bf16 hi/lo out to Ch/Cl.
// ---------------------------------------------------------------------------
#define ASTR 40                     // smem row stride (bf16), conflict-free
#define GARR (128 * ASTR)           // elements per array (10240 B)
#define GSTAGE (4 * GARR)           // Ah,Al,Bh,Bl per stage
#define GSMEM (2 * GSTAGE * 2)      // 81920 B total (2 stages)

template <int OM>
__global__ __launch_bounds__(256, 2)
void gemm_mma_kernel(const __nv_bfloat16* __restrict__ Xh,
                     const __nv_bfloat16* __restrict__ Xl,
                     const __nv_bfloat16* __restrict__ Wh,
                     const __nv_bfloat16* __restrict__ Wl,
                     const float* __restrict__ bias, float* __restrict__ Cf,
                     __nv_bfloat16* __restrict__ Ch, __nv_bfloat16* __restrict__ Cl)
{
    extern __shared__ __nv_bfloat16 gsm[];

    const int tid    = threadIdx.x;
    const int lane   = tid & 31;
    const int wid    = tid >> 5;
    const int warp_m = wid >> 2;          // 0..1  (64 rows each)
    const int warp_n = wid & 3;           // 0..3  (32 cols each)
    const int bm     = blockIdx.y * 128;
    const int bn     = blockIdx.x * 128;

    const int lrow  = tid >> 1;           // 0..127 tile row to load
    const int lhalf = (tid & 1) * 16;     // k-subrange 0..15 / 16..31

    // Per-stage smem bases (byte addresses for cp.async/ldmatrix)
    uint32_t uBase = smem_u32(gsm);
    uint32_t uAh[2], uAl[2], uBh[2], uBl[2];
#pragma unroll
    for (int s = 0; s < 2; s++) {
        uint32_t sb = uBase + s * GSTAGE * 2;
        uAh[s] = sb;
        uAl[s] = sb + GARR * 2;
        uBh[s] = sb + 2 * GARR * 2;
        uBl[s] = sb + 3 * GARR * 2;
    }
    const uint32_t stoff = (uint32_t)(lrow * ASTR + lhalf) * 2;

    float acc[4][4][4];
#pragma unroll
    for (int mf = 0; mf < 4; mf++)
#pragma unroll
        for (int nf = 0; nf < 4; nf++)
#pragma unroll
            for (int r = 0; r < 4; r++) acc[mf][nf][r] = 0.f;

    const int r0 = lane >> 2;          // 0..7
    const int c0 = (lane & 3) * 2;     // 0,2,4,6

    // ldmatrix per-lane base offsets (bytes)
    const int ja = lane >> 3, ra = lane & 7;
    const uint32_t aoff = (uint32_t)(((warp_m * 64 + (ja & 1) * 8 + ra) * ASTR
                                      + (ja >> 1) * 8) * 2);
    const uint32_t boff = (uint32_t)(((warp_n * 32 + (ja >> 1) * 8 + ra) * ASTR
                                      + (ja & 1) * 8) * 2);

    // Chunk loader: gmem -> smem stage s via cp.async (8x16B per thread)
    auto load_chunk = [&](int ch, int s) {
        const int kofs = ch * 32;
        const size_t xoff = (size_t)(bm + lrow) * D_MODEL + kofs + lhalf;
        const size_t woff = (size_t)(bn + lrow) * D_MODEL + kofs + lhalf;
        CP16(uAh[s] + stoff,      Xh + xoff);
        CP16(uAh[s] + stoff + 16, Xh + xoff + 8);
        CP16(uAl[s] + stoff,      Xl + xoff);
        CP16(uAl[s] + stoff + 16, Xl + xoff + 8);
        CP16(uBh[s] + stoff,      Wh + woff);
        CP16(uBh[s] + stoff + 16, Wh + woff + 8);
        CP16(uBl[s] + stoff,      Wl + woff);
        CP16(uBl[s] + stoff + 16, Wl + woff + 8);
        CP_COMMIT();
    };

    load_chunk(0, 0);

    const int NCH = D_MODEL / 32;   // 32
    for (int ch = 0; ch < NCH; ch++) {
        const int s = ch & 1;
        if (ch + 1 < NCH) {
            load_chunk(ch + 1, (ch + 1) & 1);
            CP_WAIT(1);
        } else {
            CP_WAIT(0);
        }
        __syncthreads();

#pragma unroll
        for (int kk = 0; kk < 32; kk += 16) {
            // B fragments: 2 x4 loads per (h,l) cover nf 0..3
            uint32_t bh[4][2], bl[4][2], t[4];
            ldsm_x4(t, uBh[s] + boff + kk * 2);
            bh[0][0] = t[0]; bh[0][1] = t[1]; bh[1][0] = t[2]; bh[1][1] = t[3];
            ldsm_x4(t, uBh[s] + boff + (16 * ASTR + kk) * 2);
            bh[2][0] = t[0]; bh[2][1] = t[1]; bh[3][0] = t[2]; bh[3][1] = t[3];
            ldsm_x4(t, uBl[s] + boff + kk * 2);
            bl[0][0] = t[0]; bl[0][1] = t[1]; bl[1][0] = t[2]; bl[1][1] = t[3];
            ldsm_x4(t, uBl[s] + boff + (16 * ASTR + kk) * 2);
            bl[2][0] = t[0]; bl[2][1] = t[1]; bl[3][0] = t[2]; bl[3][1] = t[3];

#pragma unroll
            for (int mf = 0; mf < 4; mf++) {
                uint32_t ah[4], al[4];
                ldsm_x4(ah, uAh[s] + aoff + (mf * 16 * ASTR + kk) * 2);
                ldsm_x4(al, uAl[s] + aoff + (mf * 16 * ASTR + kk) * 2);
#pragma unroll
                for (int nf = 0; nf < 4; nf++) {
                    mma16816(acc[mf][nf], ah, bh[nf]);
                    mma16816(acc[mf][nf], ah, bl[nf]);
                    mma16816(acc[mf][nf], al, bh[nf]);
                }
            }
        }
        __syncthreads();
    }

    // Epilogue
#pragma unroll
    for (int mf = 0; mf < 4; mf++) {
        int row = bm + warp_m * 64 + mf * 16 + r0;
#pragma unroll
        for (int nf = 0; nf < 4; nf++) {
            int col = bn + warp_n * 32 + nf * 8 + c0;
            float2 bv = *(const float2*)(bias + col);
            float s00 = acc[mf][nf][0] + bv.x;
            float s01 = acc[mf][nf][1] + bv.y;
            float s10 = acc[mf][nf][2] + bv.x;
            float s11 = acc[mf][nf][3] + bv.y;
            if (OM == 0) {
                *(float2*)(Cf + (size_t)row * D_MODEL + col)       = make_float2(s00, s01);
                *(float2*)(Cf + (size_t)(row + 8) * D_MODEL + col) = make_float2(s10, s11);
            } else {
                uint32_t h0, l0, h1, l1;
                split2(s00, s01, h0, l0);
                split2(s10, s11, h1, l1);
                *(uint32_t*)(Ch + (size_t)row * D_MODEL + col)       = h0;
                *(uint32_t*)(Cl + (size_t)row * D_MODEL + col)       = l0;
                *(uint32_t*)(Ch + (size_t)(row + 8) * D_MODEL + col) = h1;
                *(uint32_t*)(Cl + (size_t)(row + 8) * D_MODEL + col) = l1;
            }
        }
    }
}

// ---------------------------------------------------------------------------
// Flash attention (causal) on tensor cores, bf16 hi/lo emulated fp32.
// Block: 64 Q rows of one (n, h). 128 threads = 4 warps, each warp 16 rows.
// (unchanged from round 5 — passing at ~175us)
// ---------------------------------------------------------------------------
#define FA_STR 72                   // [64][72] bf16 tiles, conflict-free ldmatrix
#define FA_TILE (64 * FA_STR)
#define FA_SMEM (6 * FA_TILE * 2)   // 55296 B

__global__ __launch_bounds__(128, 2)
void flash_mma_kernel(const __nv_bfloat16* __restrict__ Qh_g, const __nv_bfloat16* __restrict__ Ql_g,
                      const __nv_bfloat16* __restrict__ Kh_g, const __nv_bfloat16* __restrict__ Kl_g,
                      const __nv_bfloat16* __restrict__ Vh_g, const __nv_bfloat16* __restrict__ Vl_g,
                      __nv_bfloat16* __restrict__ Oh_g, __nv_bfloat16* __restrict__ Ol_g)
{
    extern __shared__ __nv_bfloat16 fsm[];
    __nv_bfloat16* sQh = fsm;
    __nv_bfloat16* sQl = fsm + FA_TILE;
    __nv_bfloat16* sKh = fsm + 2 * FA_TILE;
    __nv_bfloat16* sKl = fsm + 3 * FA_TILE;
    __nv_bfloat16* sVh = fsm + 4 * FA_TILE;
    __nv_bfloat16* sVl = fsm + 5 * FA_TILE;

    const int tid  = threadIdx.x;
    const int lane = tid & 31;
    const int wid  = tid >> 5;
    const int qt   = blockIdx.x;
    const int h    = blockIdx.y;
    const int n    = blockIdx.z;

    const uint32_t uQh = smem_u32(sQh);
    const uint32_t uQl = smem_u32(sQl);
    const uint32_t uKh = smem_u32(sKh);
    const uint32_t uKl = smem_u32(sKl);
    const uint32_t uVh = smem_u32(sVh);
    const uint32_t uVl = smem_u32(sVl);

    const float scale = 0.125f;   // 1/sqrt(64)
    const int wr = wid * 16;      // warp's Q-row base within tile
    const int r0 = lane >> 2;     // 0..7
    const int c0 = (lane & 3) * 2;

    // Load Q tile (hi/lo), natural [row][d] layout.
    const size_t qrow0 = (size_t)(n * LSEQ + qt * 64);
    const size_t gq = qrow0 * D_MODEL + (size_t)h * HEAD_D;
#pragma unroll
    for (int i = 0; i < 4; i++) {
        int f = tid + i * 128;          // 0..511
        int row = f >> 3, c8 = (f & 7) * 8;
        int so = row * FA_STR + c8;
        size_t go = gq + (size_t)row * D_MODEL + c8;
        *(uint4*)(sQh + so) = *(const uint4*)(Qh_g + go);
        *(uint4*)(sQl + so) = *(const uint4*)(Ql_g + go);
    }

    float oacc[8][4];
#pragma unroll
    for (int nf = 0; nf < 8; nf++)
#pragma unroll
        for (int j = 0; j < 4; j++) oacc[nf][j] = 0.f;
    float m0 = -INFINITY, m1 = -INFINITY, l0 = 0.f, l1 = 0.f;

    for (int kt = 0; kt <= qt; kt++) {
        __syncthreads();   // previous iter done reading smem (also orders Q on iter 0)
        const size_t gk = ((size_t)(n * LSEQ + kt * 64)) * D_MODEL + (size_t)h * HEAD_D;
#pragma unroll
        for (int i = 0; i < 4; i++) {
            int f = tid + i * 128;      // 0..511
            int row = f >> 3, c8 = (f & 7) * 8;
            int so = row * FA_STR + c8;
            size_t go = gk + (size_t)row * D_MODEL + c8;
            *(uint4*)(sKh + so) = *(const uint4*)(Kh_g + go);
            *(uint4*)(sKl + so) = *(const uint4*)(Kl_g + go);
            *(uint4*)(sVh + so) = *(const uint4*)(Vh_g + go);
            *(uint4*)(sVl + so) = *(const uint4*)(Vl_g + go);
        }
        __syncthreads();

        // ---- S = Q K^T (hi/lo 3-product) ----
        float sacc[8][4];
#pragma unroll
        for (int nf = 0; nf < 8; nf++)
#pragma unroll
            for (int j = 0; j < 4; j++) sacc[nf][j] = 0.f;

#pragma unroll
        for (int kc = 0; kc < 4; kc++) {
            const uint32_t aoff = (uint32_t)(((wr + (lane & 15)) * FA_STR
                                  + kc * 16 + (lane >> 4) * 8) * 2);
            uint32_t aqh[4], aql[4];
            ldsm_x4(aqh, uQh + aoff);
            ldsm_x4(aql, uQl + aoff);
            const uint32_t brow = (lane & 7);
            const uint32_t bk8  = ((lane >> 3) & 1) * 8;
#pragma unroll
            for (int nf = 0; nf < 8; nf++) {
                const uint32_t boff = (uint32_t)(((nf * 8 + brow) * FA_STR
                                      + kc * 16 + bk8) * 2);
                uint32_t bkh[2], bkl[2];
                ldsm_x2(bkh, uKh + boff);
                ldsm_x2(bkl, uKl + boff);
                mma16816(sacc[nf], aqh, bkh);
                mma16816(sacc[nf], aqh, bkl);
                mma16816(sacc[nf], aql, bkh);
            }
        }

        // ---- scale + causal mask ----
        if (kt == qt) {
#pragma unroll
            for (int nf = 0; nf < 8; nf++) {
                int col = nf * 8 + c0;
                int lrA = wr + r0, lrB = wr + r0 + 8;
                sacc[nf][0] = (col     > lrA) ? -INFINITY : sacc[nf][0] * scale;
                sacc[nf][1] = (col + 1 > lrA) ? -INFINITY : sacc[nf][1] * scale;
                sacc[nf][2] = (col     > lrB) ? -INFINITY : sacc[nf][2] * scale;
                sacc[nf][3] = (col + 1 > lrB) ? -INFINITY : sacc[nf][3] * scale;
            }
        } else {
#pragma unroll
            for (int nf = 0; nf < 8; nf++)
#pragma unroll
                for (int j = 0; j < 4; j++) sacc[nf][j] *= scale;
        }

        // ---- online softmax ----
        float mx0 = -INFINITY, mx1 = -INFINITY;
#pragma unroll
        for (int nf = 0; nf < 8; nf++) {
            mx0 = fmaxf(mx0, fmaxf(sacc[nf][0], sacc[nf][1]));
            mx1 = fmaxf(mx1, fmaxf(sacc[nf][2], sacc[nf][3]));
        }
        mx0 = fmaxf(mx0, __shfl_xor_sync(0xffffffffu, mx0, 1));
        mx0 = fmaxf(mx0, __shfl_xor_sync(0xffffffffu, mx0, 2));
        mx1 = fmaxf(mx1, __shfl_xor_sync(0xffffffffu, mx1, 1));
        mx1 = fmaxf(mx1, __shfl_xor_sync(0xffffffffu, mx1, 2));
        float mn0 = fmaxf(m0, mx0), mn1 = fmaxf(m1, mx1);
        float corr0 = __expf(m0 - mn0), corr1 = __expf(m1 - mn1);
        m0 = mn0; m1 = mn1;
        float rs0 = 0.f, rs1 = 0.f;
#pragma unroll
        for (int nf = 0; nf < 8; nf++) {
            sacc[nf][0] = __expf(sacc[nf][0] - m0);
            sacc[nf][1] = __expf(sacc[nf][1] - m0);
            sacc[nf][2] = __expf(sacc[nf][2] - m1);
            sacc[nf][3] = __expf(sacc[nf][3] - m1);
            rs0 += sacc[nf][0] + sacc[nf][1];
            rs1 += sacc[nf][2] + sacc[nf][3];
        }
        rs0 += __shfl_xor_sync(0xffffffffu, rs0, 1);
        rs0 += __shfl_xor_sync(0xffffffffu, rs0, 2);
        rs1 += __shfl_xor_sync(0xffffffffu, rs1, 1);
        rs1 += __shfl_xor_sync(0xffffffffu, rs1, 2);
        l0 = l0 * corr0 + rs0;
        l1 = l1 * corr1 + rs1;
#pragma unroll
        for (int nf = 0; nf < 8; nf++) {
            oacc[nf][0] *= corr0; oacc[nf][1] *= corr0;
            oacc[nf][2] *= corr1; oacc[nf][3] *= corr1;
        }

        // ---- O += P V (hi/lo 3-product, P repacked from accumulators) ----
#pragma unroll
        for (int kc = 0; kc < 4; kc++) {
            uint32_t aph[4], apl[4];
            split2(sacc[2 * kc][0],     sacc[2 * kc][1],     aph[0], apl[0]);
            split2(sacc[2 * kc][2],     sacc[2 * kc][3],     aph[1], apl[1]);
            split2(sacc[2 * kc + 1][0], sacc[2 * kc + 1][1], aph[2], apl[2]);
            split2(sacc[2 * kc + 1][2], sacc[2 * kc + 1][3], aph[3], apl[3]);
            const uint32_t vrow = (uint32_t)(kc * 16 + (lane & 15));
#pragma unroll
            for (int nf = 0; nf < 8; nf++) {
                const uint32_t voff = (uint32_t)((vrow * FA_STR + nf * 8) * 2);
                uint32_t bvh[2], bvl[2];
                ldsm_x2t(bvh, uVh + voff);
                ldsm_x2t(bvl, uVl + voff);
                mma16816(oacc[nf], aph, bvh);
                mma16816(oacc[nf], aph, bvl);
                mma16816(oacc[nf], apl, bvh);
            }
        }
    }

    // ---- epilogue: normalize, split to bf16 hi/lo, store ----
    float inv0 = 1.f / l0, inv1 = 1.f / l1;
    const size_t goA = (qrow0 + wr + r0) * D_MODEL + (size_t)h * HEAD_D;
    const size_t goB = goA + 8 * D_MODEL;
#pragma unroll
    for (int nf = 0; nf < 8; nf++) {
        int d = nf * 8 + c0;
        uint32_t h0, lo0, h1, lo1;
        split2(oacc[nf][0] * inv0, oacc[nf][1] * inv0, h0, lo0);
        split2(oacc[nf][2] * inv1, oacc[nf][3] * inv1, h1, lo1);
        *(uint32_t*)(Oh_g + goA + d) = h0;
        *(uint32_t*)(Ol_g + goA + d) = lo0;
        *(uint32_t*)(Oh_g + goB + d) = h1;
        *(uint32_t*)(Ol_g + goB + d) = lo1;
    }
}

// ---------------------------------------------------------------------------
// kernel_launch
// ---------------------------------------------------------------------------
extern "C" void kernel_launch(void* const* d_in, const int* in_sizes, int n_in,
                              void* d_out, int out_size)
{
    const float* queries = (const float*)d_in[0];
    const float* keys    = (const float*)d_in[1];
    const float* values  = (const float*)d_in[2];
    const float* Wq = (const float*)d_in[3];
    const float* bq = (const float*)d_in[4];
    const float* Wk = (const float*)d_in[5];
    const float* bk = (const float*)d_in[6];
    const float* Wv = (const float*)d_in[7];
    const float* bv = (const float*)d_in[8];
    const float* Wo = (const float*)d_in[9];
    const float* bo = (const float*)d_in[10];
    float* out = (float*)d_out;

    __nv_bfloat16 *xh, *xl, *wh, *wl, *qh, *ql, *kh, *kl, *vh, *vl, *ah, *al;
    cudaGetSymbolAddress((void**)&xh, g_xh);
    cudaGetSymbolAddress((void**)&xl, g_xl);
    cudaGetSymbolAddress((void**)&wh, g_wh);
    cudaGetSymbolAddress((void**)&wl, g_wl);
    cudaGetSymbolAddress((void**)&qh, g_qh);
    cudaGetSymbolAddress((void**)&ql, g_ql);
    cudaGetSymbolAddress((void**)&kh, g_kh);
    cudaGetSymbolAddress((void**)&kl, g_kl);
    cudaGetSymbolAddress((void**)&vh, g_vh);
    cudaGetSymbolAddress((void**)&vl, g_vl);
    cudaGetSymbolAddress((void**)&ah, g_ah);
    cudaGetSymbolAddress((void**)&al, g_al);

    const size_t XSZ = (size_t)MTOT * D_MODEL;     // 4M elements
    const size_t WSZ = (size_t)D_MODEL * D_MODEL;  // 1M elements
    const int XB = (int)(XSZ / 4 / 256);
    const int WB = (int)(WSZ / 4 / 256);

    cudaFuncSetAttribute(flash_mma_kernel,
                         cudaFuncAttributeMaxDynamicSharedMemorySize, FA_SMEM);
    cudaFuncSetAttribute(gemm_mma_kernel<0>,
                         cudaFuncAttributeMaxDynamicSharedMemorySize, GSMEM);
    cudaFuncSetAttribute(gemm_mma_kernel<1>,
                         cudaFuncAttributeMaxDynamicSharedMemorySize, GSMEM);

    // Split inputs and weights to bf16 hi/lo
    split_bf16_kernel<<<XB, 256>>>(queries, xh,           xl,           (int)(XSZ / 4));
    split_bf16_kernel<<<XB, 256>>>(keys,    xh + XSZ,     xl + XSZ,     (int)(XSZ / 4));
    split_bf16_kernel<<<XB, 256>>>(values,  xh + 2 * XSZ, xl + 2 * XSZ, (int)(XSZ / 4));
    split_bf16_kernel<<<WB, 256>>>(Wq, wh,           wl,           (int)(WSZ / 4));
    split_bf16_kernel<<<WB, 256>>>(Wk, wh + WSZ,     wl + WSZ,     (int)(WSZ / 4));
    split_bf16_kernel<<<WB, 256>>>(Wv, wh + 2 * WSZ, wl + 2 * WSZ, (int)(WSZ / 4));
    split_bf16_kernel<<<WB, 256>>>(Wo, wh + 3 * WSZ, wl + 3 * WSZ, (int)(WSZ / 4));

    dim3 gBlk(256);
    dim3 gGrd(D_MODEL / 128, MTOT / 128);   // (8, 32)

    // Projections: emit bf16 hi/lo directly
    gemm_mma_kernel<1><<<gGrd, gBlk, GSMEM>>>(xh,           xl,           wh,           wl,           bq, nullptr, qh, ql);
    gemm_mma_kernel<1><<<gGrd, gBlk, GSMEM>>>(xh + XSZ,     xl + XSZ,     wh + WSZ,     wl + WSZ,     bk, nullptr, kh, kl);
    gemm_mma_kernel<1><<<gGrd, gBlk, GSMEM>>>(xh + 2 * XSZ, xl + 2 * XSZ, wh + 2 * WSZ, wl + 2 * WSZ, bv, nullptr, vh, vl);

    // Attention on tensor cores, emits hi/lo
    dim3 aGrd(LSEQ / 64, N_HEADS, NB);      // (32, 16, 2)
    flash_mma_kernel<<<aGrd, 128, FA_SMEM>>>(qh, ql, kh, kl, vh, vl, ah, al);

    // Output projection: fp32 out
    gemm_mma_kernel<0><<<gGrd, gBlk, GSMEM>>>(ah, al, wh + 3 * WSZ, wl + 3 * WSZ, bo, out, nullptr, nullptr);
}

// round 7
// speedup vs baseline: 2.5140x; 1.0515x over previous
#include <cuda_runtime.h>
#include <cuda_bf16.h>
#include <cstdint>
#include <math.h>

// Problem constants (fixed shapes from reference)
#define D_MODEL 1024
#define N_HEADS 16
#define HEAD_D  64
#define NB      2
#define LSEQ    2048
#define MTOT    (NB * LSEQ)   // 4096 rows total

#define XSZ ((size_t)MTOT * D_MODEL)     // 4M elements
#define WSZ ((size_t)D_MODEL * D_MODEL)  // 1M elements

// ---------------------------------------------------------------------------
// Scratch (allocation-free rule: __device__ globals) — all bf16 hi/lo pairs
// ---------------------------------------------------------------------------
__device__ __nv_bfloat16 g_xh[3][XSZ];   // q/k/v inputs hi
__device__ __nv_bfloat16 g_xl[3][XSZ];   // lo
__device__ __nv_bfloat16 g_wh[4][WSZ];   // Wq/Wk/Wv/Wo hi
__device__ __nv_bfloat16 g_wl[4][WSZ];   // lo
__device__ __nv_bfloat16 g_qh[XSZ];      // projected Q hi/lo
__device__ __nv_bfloat16 g_ql[XSZ];
__device__ __nv_bfloat16 g_kh[XSZ];
__device__ __nv_bfloat16 g_kl[XSZ];
__device__ __nv_bfloat16 g_vh[XSZ];
__device__ __nv_bfloat16 g_vl[XSZ];
__device__ __nv_bfloat16 g_ah[XSZ];      // attn out hi/lo
__device__ __nv_bfloat16 g_al[XSZ];

// ---------------------------------------------------------------------------
// Small helpers
// ---------------------------------------------------------------------------
__device__ __forceinline__ uint32_t smem_u32(const void* p) {
    uint32_t a;
    asm("{ .reg .u64 t; cvta.to.shared.u64 t, %1; cvt.u32.u64 %0, t; }"
        : "=r"(a) : "l"(p));
    return a;
}
__device__ __forceinline__ void split2(float x, float y, uint32_t& hi, uint32_t& lo) {
    __nv_bfloat16 hx = __float2bfloat16_rn(x), hy = __float2bfloat16_rn(y);
    __nv_bfloat162 hp; hp.x = hx; hp.y = hy;
    hi = *reinterpret_cast<uint32_t*>(&hp);
    __nv_bfloat162 lp = __floats2bfloat162_rn(x - __bfloat162float(hx),
                                              y - __bfloat162float(hy));
    lo = *reinterpret_cast<uint32_t*>(&lp);
}
__device__ __forceinline__ void mma16816(float* c, const uint32_t* a, const uint32_t* b) {
    asm volatile(
        "mma.sync.aligned.m16n8k16.row.col.f32.bf16.bf16.f32 "
        "{%0,%1,%2,%3}, {%4,%5,%6,%7}, {%8,%9}, {%0,%1,%2,%3};"
        : "+f"(c[0]), "+f"(c[1]), "+f"(c[2]), "+f"(c[3])
        : "r"(a[0]), "r"(a[1]), "r"(a[2]), "r"(a[3]), "r"(b[0]), "r"(b[1]));
}
__device__ __forceinline__ void ldsm_x4(uint32_t* r, uint32_t a) {
    asm volatile("ldmatrix.sync.aligned.m8n8.x4.shared.b16 {%0,%1,%2,%3},[%4];"
                 : "=r"(r[0]), "=r"(r[1]), "=r"(r[2]), "=r"(r[3]) : "r"(a));
}
__device__ __forceinline__ void ldsm_x2(uint32_t* r, uint32_t a) {
    asm volatile("ldmatrix.sync.aligned.m8n8.x2.shared.b16 {%0,%1},[%2];"
                 : "=r"(r[0]), "=r"(r[1]) : "r"(a));
}
__device__ __forceinline__ void ldsm_x2t(uint32_t* r, uint32_t a) {
    asm volatile("ldmatrix.sync.aligned.m8n8.x2.trans.shared.b16 {%0,%1},[%2];"
                 : "=r"(r[0]), "=r"(r[1]) : "r"(a));
}
#define CP16(dst, src) \
    asm volatile("cp.async.cg.shared.global [%0], [%1], 16;" \
                 :: "r"(dst), "l"(src) : "memory")
#define CP_COMMIT() asm volatile("cp.async.commit_group;" ::: "memory")
#define CP_WAIT(n)  asm volatile("cp.async.wait_group %0;" :: "n"(n) : "memory")

// ---------------------------------------------------------------------------
// Fused fp32 -> bf16 hi/lo split for all 7 tensors. blockIdx.y = tensor.
// y 0..2: inputs (XSZ); y 3..6: weights (WSZ).
// ---------------------------------------------------------------------------
__global__ __launch_bounds__(256)
void split_all_kernel(const float* __restrict__ sx0, const float* __restrict__ sx1,
                      const float* __restrict__ sx2,
                      const float* __restrict__ sw0, const float* __restrict__ sw1,
                      const float* __restrict__ sw2, const float* __restrict__ sw3,
                      __nv_bfloat16* __restrict__ xh, __nv_bfloat16* __restrict__ xl,
                      __nv_bfloat16* __restrict__ wh, __nv_bfloat16* __restrict__ wl)
{
    const int t = blockIdx.y;
    const float* src;
    __nv_bfloat16 *hi, *lo;
    int n4;
    if (t < 3) {
        src = (t == 0) ? sx0 : (t == 1) ? sx1 : sx2;
        hi = xh + (size_t)t * XSZ;
        lo = xl + (size_t)t * XSZ;
        n4 = (int)(XSZ / 4);
    } else {
        int w = t - 3;
        src = (w == 0) ? sw0 : (w == 1) ? sw1 : (w == 2) ? sw2 : sw3;
        hi = wh + (size_t)w * WSZ;
        lo = wl + (size_t)w * WSZ;
        n4 = (int)(WSZ / 4);
    }
    int i = blockIdx.x * blockDim.x + threadIdx.x;
    if (i >= n4) return;
    float4 v = ((const float4*)src)[i];
    uint32_t h0, l0, h1, l1;
    split2(v.x, v.y, h0, l0);
    split2(v.z, v.w, h1, l1);
    ((uint2*)hi)[i] = make_uint2(h0, h1);
    ((uint2*)lo)[i] = make_uint2(l0, l1);
}

// ---------------------------------------------------------------------------
// GEMM core: C[m,n] = sum_k X[m,k]*W[n,k] (+bias). 128x128 tile, K chunk 32,
// 256 threads = 8 warps. 2-stage cp.async pipeline, ldmatrix fragments.
// ---------------------------------------------------------------------------
#define ASTR 40                     // smem row stride (bf16), conflict-free
#define GARR (128 * ASTR)           // elements per array (10240 B)
#define GSTAGE (4 * GARR)           // Ah,Al,Bh,Bl per stage
#define GSMEM (2 * GSTAGE * 2)      // 81920 B total (2 stages)

struct GemmCore {
    uint32_t uAh[2], uAl[2], uBh[2], uBl[2];
    uint32_t stoff, aoff, boff;
    int lrow, lhalf, warp_m, warp_n, r0, c0;
    float acc[4][4][4];

    __device__ __forceinline__ void init(__nv_bfloat16* gsm, int tid) {
        const int lane = tid & 31;
        const int wid  = tid >> 5;
        warp_m = wid >> 2;
        warp_n = wid & 3;
        lrow  = tid >> 1;
        lhalf = (tid & 1) * 16;
        r0 = lane >> 2;
        c0 = (lane & 3) * 2;
        uint32_t uBase = smem_u32(gsm);
#pragma unroll
        for (int s = 0; s < 2; s++) {
            uint32_t sb = uBase + s * GSTAGE * 2;
            uAh[s] = sb;
            uAl[s] = sb + GARR * 2;
            uBh[s] = sb + 2 * GARR * 2;
            uBl[s] = sb + 3 * GARR * 2;
        }
        stoff = (uint32_t)(lrow * ASTR + lhalf) * 2;
        const int ja = lane >> 3, ra = lane & 7;
        aoff = (uint32_t)(((warp_m * 64 + (ja & 1) * 8 + ra) * ASTR + (ja >> 1) * 8) * 2);
        boff = (uint32_t)(((warp_n * 32 + (ja >> 1) * 8 + ra) * ASTR + (ja & 1) * 8) * 2);
#pragma unroll
        for (int mf = 0; mf < 4; mf++)
#pragma unroll
            for (int nf = 0; nf < 4; nf++)
#pragma unroll
                for (int r = 0; r < 4; r++) acc[mf][nf][r] = 0.f;
    }

    __device__ __forceinline__ void load_chunk(
        const __nv_bfloat16* Xh, const __nv_bfloat16* Xl,
        const __nv_bfloat16* Wh, const __nv_bfloat16* Wl,
        int bm, int bn, int ch, int s)
    {
        const int kofs = ch * 32;
        const size_t xoff = (size_t)(bm + lrow) * D_MODEL + kofs + lhalf;
        const size_t woff = (size_t)(bn + lrow) * D_MODEL + kofs + lhalf;
        CP16(uAh[s] + stoff,      Xh + xoff);
        CP16(uAh[s] + stoff + 16, Xh + xoff + 8);
        CP16(uAl[s] + stoff,      Xl + xoff);
        CP16(uAl[s] + stoff + 16, Xl + xoff + 8);
        CP16(uBh[s] + stoff,      Wh + woff);
        CP16(uBh[s] + stoff + 16, Wh + woff + 8);
        CP16(uBl[s] + stoff,      Wl + woff);
        CP16(uBl[s] + stoff + 16, Wl + woff + 8);
        CP_COMMIT();
    }

    __device__ __forceinline__ void compute_chunk(int s) {
#pragma unroll
        for (int kk = 0; kk < 32; kk += 16) {
            uint32_t bh[4][2], bl[4][2], t[4];
            ldsm_x4(t, uBh[s] + boff + kk * 2);
            bh[0][0] = t[0]; bh[0][1] = t[1]; bh[1][0] = t[2]; bh[1][1] = t[3];
            ldsm_x4(t, uBh[s] + boff + (16 * ASTR + kk) * 2);
            bh[2][0] = t[0]; bh[2][1] = t[1]; bh[3][0] = t[2]; bh[3][1] = t[3];
            ldsm_x4(t, uBl[s] + boff + kk * 2);
            bl[0][0] = t[0]; bl[0][1] = t[1]; bl[1][0] = t[2]; bl[1][1] = t[3];
            ldsm_x4(t, uBl[s] + boff + (16 * ASTR + kk) * 2);
            bl[2][0] = t[0]; bl[2][1] = t[1]; bl[3][0] = t[2]; bl[3][1] = t[3];

#pragma unroll
            for (int mf = 0; mf < 4; mf++) {
                uint32_t ah[4], al[4];
                ldsm_x4(ah, uAh[s] + aoff + (mf * 16 * ASTR + kk) * 2);
                ldsm_x4(al, uAl[s] + aoff + (mf * 16 * ASTR + kk) * 2);
#pragma unroll
                for (int nf = 0; nf < 4; nf++) {
                    mma16816(acc[mf][nf], ah, bh[nf]);
                    mma16816(acc[mf][nf], ah, bl[nf]);
                    mma16816(acc[mf][nf], al, bh[nf]);
                }
            }
        }
    }

    __device__ __forceinline__ void run(
        const __nv_bfloat16* Xh, const __nv_bfloat16* Xl,
        const __nv_bfloat16* Wh, const __nv_bfloat16* Wl, int bm, int bn)
    {
        load_chunk(Xh, Xl, Wh, Wl, bm, bn, 0, 0);
        const int NCH = D_MODEL / 32;   // 32
        for (int ch = 0; ch < NCH; ch++) {
            const int s = ch & 1;
            if (ch + 1 < NCH) {
                load_chunk(Xh, Xl, Wh, Wl, bm, bn, ch + 1, s ^ 1);
                CP_WAIT(1);
            } else {
                CP_WAIT(0);
            }
            __syncthreads();
            compute_chunk(s);
            __syncthreads();
        }
    }
};

// Batched QKV projection: blockIdx.z selects (input, weight, bias, output).
__global__ __launch_bounds__(256, 2)
void gemm_qkv_kernel(const __nv_bfloat16* __restrict__ xh, const __nv_bfloat16* __restrict__ xl,
                     const __nv_bfloat16* __restrict__ wh, const __nv_bfloat16* __restrict__ wl,
                     const float* __restrict__ bq, const float* __restrict__ bk,
                     const float* __restrict__ bv,
                     __nv_bfloat16* __restrict__ qh, __nv_bfloat16* __restrict__ ql,
                     __nv_bfloat16* __restrict__ kh, __nv_bfloat16* __restrict__ kl,
                     __nv_bfloat16* __restrict__ vh, __nv_bfloat16* __restrict__ vl)
{
    extern __shared__ __nv_bfloat16 gsm[];
    const int t  = blockIdx.z;
    const int bm = blockIdx.y * 128;
    const int bn = blockIdx.x * 128;

    const __nv_bfloat16* Xh = xh + (size_t)t * XSZ;
    const __nv_bfloat16* Xl = xl + (size_t)t * XSZ;
    const __nv_bfloat16* Wh = wh + (size_t)t * WSZ;
    const __nv_bfloat16* Wl = wl + (size_t)t * WSZ;
    const float* bias = (t == 0) ? bq : (t == 1) ? bk : bv;
    __nv_bfloat16* Ch = (t == 0) ? qh : (t == 1) ? kh : vh;
    __nv_bfloat16* Cl = (t == 0) ? ql : (t == 1) ? kl : vl;

    GemmCore g;
    g.init(gsm, threadIdx.x);
    g.run(Xh, Xl, Wh, Wl, bm, bn);

#pragma unroll
    for (int mf = 0; mf < 4; mf++) {
        int row = bm + g.warp_m * 64 + mf * 16 + g.r0;
#pragma unroll
        for (int nf = 0; nf < 4; nf++) {
            int col = bn + g.warp_n * 32 + nf * 8 + g.c0;
            float2 bv2 = *(const float2*)(bias + col);
            uint32_t h0, l0, h1, l1;
            split2(g.acc[mf][nf][0] + bv2.x, g.acc[mf][nf][1] + bv2.y, h0, l0);
            split2(g.acc[mf][nf][2] + bv2.x, g.acc[mf][nf][3] + bv2.y, h1, l1);
            *(uint32_t*)(Ch + (size_t)row * D_MODEL + col)       = h0;
            *(uint32_t*)(Cl + (size_t)row * D_MODEL + col)       = l0;
            *(uint32_t*)(Ch + (size_t)(row + 8) * D_MODEL + col) = h1;
            *(uint32_t*)(Cl + (size_t)(row + 8) * D_MODEL + col) = l1;
        }
    }
}

// Output projection: fp32 out.
__global__ __launch_bounds__(256, 2)
void gemm_o_kernel(const __nv_bfloat16* __restrict__ Xh, const __nv_bfloat16* __restrict__ Xl,
                   const __nv_bfloat16* __restrict__ Wh, const __nv_bfloat16* __restrict__ Wl,
                   const float* __restrict__ bias, float* __restrict__ Cf)
{
    extern __shared__ __nv_bfloat16 gsm[];
    const int bm = blockIdx.y * 128;
    const int bn = blockIdx.x * 128;

    GemmCore g;
    g.init(gsm, threadIdx.x);
    g.run(Xh, Xl, Wh, Wl, bm, bn);

#pragma unroll
    for (int mf = 0; mf < 4; mf++) {
        int row = bm + g.warp_m * 64 + mf * 16 + g.r0;
#pragma unroll
        for (int nf = 0; nf < 4; nf++) {
            int col = bn + g.warp_n * 32 + nf * 8 + g.c0;
            float2 bv2 = *(const float2*)(bias + col);
            *(float2*)(Cf + (size_t)row * D_MODEL + col) =
                make_float2(g.acc[mf][nf][0] + bv2.x, g.acc[mf][nf][1] + bv2.y);
            *(float2*)(Cf + (size_t)(row + 8) * D_MODEL + col) =
                make_float2(g.acc[mf][nf][2] + bv2.x, g.acc[mf][nf][3] + bv2.y);
        }
    }
}

// ---------------------------------------------------------------------------
// Flash attention (causal) on tensor cores, bf16 hi/lo emulated fp32.
// Block: 64 Q rows of one (n, h). 128 threads = 4 warps, each warp 16 rows.
// K/V tiles double-buffered via cp.async; 1 barrier per kt iteration.
// ---------------------------------------------------------------------------
#define FA_STR 72                   // [64][72] bf16 tiles, conflict-free ldmatrix
#define FA_TILE (64 * FA_STR)       // elements per array
#define FT2 (FA_TILE * 2)           // bytes per array (9216)
#define FA_SMEM (10 * FT2)          // Q(2) + 2 stages x KV(4) = 92160 B

__global__ __launch_bounds__(128, 2)
void flash_mma_kernel(const __nv_bfloat16* __restrict__ Qh_g, const __nv_bfloat16* __restrict__ Ql_g,
                      const __nv_bfloat16* __restrict__ Kh_g, const __nv_bfloat16* __restrict__ Kl_g,
                      const __nv_bfloat16* __restrict__ Vh_g, const __nv_bfloat16* __restrict__ Vl_g,
                      __nv_bfloat16* __restrict__ Oh_g, __nv_bfloat16* __restrict__ Ol_g)
{
    extern __shared__ __nv_bfloat16 fsm[];
    __nv_bfloat16* sQh = fsm;
    __nv_bfloat16* sQl = fsm + FA_TILE;

    const int tid  = threadIdx.x;
    const int lane = tid & 31;
    const int wid  = tid >> 5;
    const int qt   = blockIdx.x;
    const int h    = blockIdx.y;
    const int n    = blockIdx.z;

    const uint32_t uQh = smem_u32(sQh);
    const uint32_t uQl = smem_u32(sQl);
    const uint32_t uKV0 = uQh + 2 * FT2;   // stage 0 base
    // per stage s: Kh = uKV0 + s*4*FT2; Kl = +FT2; Vh = +2*FT2; Vl = +3*FT2

    const float scale = 0.125f;   // 1/sqrt(64)
    const int wr = wid * 16;      // warp's Q-row base within tile
    const int r0 = lane >> 2;     // 0..7
    const int c0 = (lane & 3) * 2;

    // Load Q tile (hi/lo), natural [row][d] layout (plain vector loads).
    const size_t qrow0 = (size_t)(n * LSEQ + qt * 64);
    const size_t gq = qrow0 * D_MODEL + (size_t)h * HEAD_D;
#pragma unroll
    for (int i = 0; i < 4; i++) {
        int f = tid + i * 128;          // 0..511
        int row = f >> 3, c8 = (f & 7) * 8;
        int so = row * FA_STR + c8;
        size_t go = gq + (size_t)row * D_MODEL + c8;
        *(uint4*)(sQh + so) = *(const uint4*)(Qh_g + go);
        *(uint4*)(sQl + so) = *(const uint4*)(Ql_g + go);
    }

    // K/V chunk loader via cp.async (16x16B per thread)
    auto load_kv = [&](int kt, int s) {
        const uint32_t base = uKV0 + (uint32_t)s * 4 * FT2;
        const size_t gk = ((size_t)(n * LSEQ + kt * 64)) * D_MODEL + (size_t)h * HEAD_D;
#pragma unroll
        for (int i = 0; i < 4; i++) {
            int f = tid + i * 128;
            int row = f >> 3, c8 = (f & 7) * 8;
            uint32_t so = (uint32_t)(row * FA_STR + c8) * 2;
            size_t go = gk + (size_t)row * D_MODEL + c8;
            CP16(base + so,           Kh_g + go);
            CP16(base + FT2 + so,     Kl_g + go);
            CP16(base + 2 * FT2 + so, Vh_g + go);
            CP16(base + 3 * FT2 + so, Vl_g + go);
        }
        CP_COMMIT();
    };

    float oacc[8][4];
#pragma unroll
    for (int nf = 0; nf < 8; nf++)
#pragma unroll
        for (int j = 0; j < 4; j++) oacc[nf][j] = 0.f;
    float m0 = -INFINITY, m1 = -INFINITY, l0 = 0.f, l1 = 0.f;

    load_kv(0, 0);

    for (int kt = 0; kt <= qt; kt++) {
        const int s = kt & 1;
        const uint32_t uKh = uKV0 + (uint32_t)s * 4 * FT2;
        const uint32_t uKl = uKh + FT2;
        const uint32_t uVh = uKh + 2 * FT2;
        const uint32_t uVl = uKh + 3 * FT2;

        CP_WAIT(0);        // current stage's copies arrived
        __syncthreads();   // all warps done with stage s^1 (prev compute) + copies visible
        if (kt < qt) load_kv(kt + 1, s ^ 1);   // prefetch overlaps compute below

        // ---- S = Q K^T (hi/lo 3-product) ----
        float sacc[8][4];
#pragma unroll
        for (int nf = 0; nf < 8; nf++)
#pragma unroll
            for (int j = 0; j < 4; j++) sacc[nf][j] = 0.f;

#pragma unroll
        for (int kc = 0; kc < 4; kc++) {
            const uint32_t aoff = (uint32_t)(((wr + (lane & 15)) * FA_STR
                                  + kc * 16 + (lane >> 4) * 8) * 2);
            uint32_t aqh[4], aql[4];
            ldsm_x4(aqh, uQh + aoff);
            ldsm_x4(aql, uQl + aoff);
            const uint32_t brow = (lane & 7);
            const uint32_t bk8  = ((lane >> 3) & 1) * 8;
#pragma unroll
            for (int nf = 0; nf < 8; nf++) {
                const uint32_t boff = (uint32_t)(((nf * 8 + brow) * FA_STR
                                      + kc * 16 + bk8) * 2);
                uint32_t bkh[2], bkl[2];
                ldsm_x2(bkh, uKh + boff);
                ldsm_x2(bkl, uKl + boff);
                mma16816(sacc[nf], aqh, bkh);
                mma16816(sacc[nf], aqh, bkl);
                mma16816(sacc[nf], aql, bkh);
            }
        }

        // ---- scale + causal mask ----
        if (kt == qt) {
#pragma unroll
            for (int nf = 0; nf < 8; nf++) {
                int col = nf * 8 + c0;
                int lrA = wr + r0, lrB = wr + r0 + 8;
                sacc[nf][0] = (col     > lrA) ? -INFINITY : sacc[nf][0] * scale;
                sacc[nf][1] = (col + 1 > lrA) ? -INFINITY : sacc[nf][1] * scale;
                sacc[nf][2] = (col     > lrB) ? -INFINITY : sacc[nf][2] * scale;
                sacc[nf][3] = (col + 1 > lrB) ? -INFINITY : sacc[nf][3] * scale;
            }
        } else {
#pragma unroll
            for (int nf = 0; nf < 8; nf++)
#pragma unroll
                for (int j = 0; j < 4; j++) sacc[nf][j] *= scale;
        }

        // ---- online softmax ----
        float mx0 = -INFINITY, mx1 = -INFINITY;
#pragma unroll
        for (int nf = 0; nf < 8; nf++) {
            mx0 = fmaxf(mx0, fmaxf(sacc[nf][0], sacc[nf][1]));
            mx1 = fmaxf(mx1, fmaxf(sacc[nf][2], sacc[nf][3]));
        }
        mx0 = fmaxf(mx0, __shfl_xor_sync(0xffffffffu, mx0, 1));
        mx0 = fmaxf(mx0, __shfl_xor_sync(0xffffffffu, mx0, 2));
        mx1 = fmaxf(mx1, __shfl_xor_sync(0xffffffffu, mx1, 1));
        mx1 = fmaxf(mx1, __shfl_xor_sync(0xffffffffu, mx1, 2));
        float mn0 = fmaxf(m0, mx0), mn1 = fmaxf(m1, mx1);
        float corr0 = __expf(m0 - mn0), corr1 = __expf(m1 - mn1);
        m0 = mn0; m1 = mn1;
        float rs0 = 0.f, rs1 = 0.f;
#pragma unroll
        for (int nf = 0; nf < 8; nf++) {
            sacc[nf][0] = __expf(sacc[nf][0] - m0);
            sacc[nf][1] = __expf(sacc[nf][1] - m0);
            sacc[nf][2] = __expf(sacc[nf][2] - m1);
            sacc[nf][3] = __expf(sacc[nf][3] - m1);
            rs0 += sacc[nf][0] + sacc[nf][1];
            rs1 += sacc[nf][2] + sacc[nf][3];
        }
        rs0 += __shfl_xor_sync(0xffffffffu, rs0, 1);
        rs0 += __shfl_xor_sync(0xffffffffu, rs0, 2);
        rs1 += __shfl_xor_sync(0xffffffffu, rs1, 1);
        rs1 += __shfl_xor_sync(0xffffffffu, rs1, 2);
        l0 = l0 * corr0 + rs0;
        l1 = l1 * corr1 + rs1;
#pragma unroll
        for (int nf = 0; nf < 8; nf++) {
            oacc[nf][0] *= corr0; oacc[nf][1] *= corr0;
            oacc[nf][2] *= corr1; oacc[nf][3] *= corr1;
        }

        // ---- O += P V (hi/lo 3-product, P repacked from accumulators) ----
#pragma unroll
        for (int kc = 0; kc < 4; kc++) {
            uint32_t aph[4], apl[4];
            split2(sacc[2 * kc][0],     sacc[2 * kc][1],     aph[0], apl[0]);
            split2(sacc[2 * kc][2],     sacc[2 * kc][3],     aph[1], apl[1]);
            split2(sacc[2 * kc + 1][0], sacc[2 * kc + 1][1], aph[2], apl[2]);
            split2(sacc[2 * kc + 1][2], sacc[2 * kc + 1][3], aph[3], apl[3]);
            const uint32_t vrow = (uint32_t)(kc * 16 + (lane & 15));
#pragma unroll
            for (int nf = 0; nf < 8; nf++) {
                const uint32_t voff = (uint32_t)((vrow * FA_STR + nf * 8) * 2);
                uint32_t bvh[2], bvl[2];
                ldsm_x2t(bvh, uVh + voff);
                ldsm_x2t(bvl, uVl + voff);
                mma16816(oacc[nf], aph, bvh);
                mma16816(oacc[nf], aph, bvl);
                mma16816(oacc[nf], apl, bvh);
            }
        }
    }

    // ---- epilogue: normalize, split to bf16 hi/lo, store ----
    float inv0 = 1.f / l0, inv1 = 1.f / l1;
    const size_t goA = (qrow0 + wr + r0) * D_MODEL + (size_t)h * HEAD_D;
    const size_t goB = goA + 8 * D_MODEL;
#pragma unroll
    for (int nf = 0; nf < 8; nf++) {
        int d = nf * 8 + c0;
        uint32_t h0, lo0, h1, lo1;
        split2(oacc[nf][0] * inv0, oacc[nf][1] * inv0, h0, lo0);
        split2(oacc[nf][2] * inv1, oacc[nf][3] * inv1, h1, lo1);
        *(uint32_t*)(Oh_g + goA + d) = h0;
        *(uint32_t*)(Ol_g + goA + d) = lo0;
        *(uint32_t*)(Oh_g + goB + d) = h1;
        *(uint32_t*)(Ol_g + goB + d) = lo1;
    }
}

// ---------------------------------------------------------------------------
// kernel_launch: split(1) -> gemm_qkv(1) -> flash(1) -> gemm_o(1)
// ---------------------------------------------------------------------------
extern "C" void kernel_launch(void* const* d_in, const int* in_sizes, int n_in,
                              void* d_out, int out_size)
{
    const float* queries = (const float*)d_in[0];
    const float* keys    = (const float*)d_in[1];
    const float* values  = (const float*)d_in[2];
    const float* Wq = (const float*)d_in[3];
    const float* bq = (const float*)d_in[4];
    const float* Wk = (const float*)d_in[5];
    const float* bk = (const float*)d_in[6];
    const float* Wv = (const float*)d_in[7];
    const float* bv = (const float*)d_in[8];
    const float* Wo = (const float*)d_in[9];
    const float* bo = (const float*)d_in[10];
    float* out = (float*)d_out;

    __nv_bfloat16 *xh, *xl, *wh, *wl, *qh, *ql, *kh, *kl, *vh, *vl, *ah, *al;
    cudaGetSymbolAddress((void**)&xh, g_xh);
    cudaGetSymbolAddress((void**)&xl, g_xl);
    cudaGetSymbolAddress((void**)&wh, g_wh);
    cudaGetSymbolAddress((void**)&wl, g_wl);
    cudaGetSymbolAddress((void**)&qh, g_qh);
    cudaGetSymbolAddress((void**)&ql, g_ql);
    cudaGetSymbolAddress((void**)&kh, g_kh);
    cudaGetSymbolAddress((void**)&kl, g_kl);
    cudaGetSymbolAddress((void**)&vh, g_vh);
    cudaGetSymbolAddress((void**)&vl, g_vl);
    cudaGetSymbolAddress((void**)&ah, g_ah);
    cudaGetSymbolAddress((void**)&al, g_al);

    cudaFuncSetAttribute(flash_mma_kernel,
                         cudaFuncAttributeMaxDynamicSharedMemorySize, FA_SMEM);
    cudaFuncSetAttribute(gemm_qkv_kernel,
                         cudaFuncAttributeMaxDynamicSharedMemorySize, GSMEM);
    cudaFuncSetAttribute(gemm_o_kernel,
                         cudaFuncAttributeMaxDynamicSharedMemorySize, GSMEM);

    // 1) Fused split of all 7 tensors
    dim3 sGrd((unsigned)(XSZ / 4 / 256), 7);
    split_all_kernel<<<sGrd, 256>>>(queries, keys, values, Wq, Wk, Wv, Wo,
                                    xh, xl, wh, wl);

    // 2) Batched Q/K/V projections (z = tensor)
    dim3 gGrd(D_MODEL / 128, MTOT / 128, 3);   // (8, 32, 3)
    gemm_qkv_kernel<<<gGrd, 256, GSMEM>>>(xh, xl, wh, wl, bq, bk, bv,
                                          qh, ql, kh, kl, vh, vl);

    // 3) Attention on tensor cores, emits hi/lo
    dim3 aGrd(LSEQ / 64, N_HEADS, NB);         // (32, 16, 2)
    flash_mma_kernel<<<aGrd, 128, FA_SMEM>>>(qh, ql, kh, kl, vh, vl, ah, al);

    // 4) Output projection: fp32 out
    dim3 oGrd(D_MODEL / 128, MTOT / 128);      // (8, 32)
    gemm_o_kernel<<<oGrd, 256, GSMEM>>>(ah, al, wh + 3 * WSZ, wl + 3 * WSZ, bo, out);
}